// round 3
// baseline (speedup 1.0000x reference)
#include <cuda_runtime.h>
#include <cuda_bf16.h>
#include <cstdint>
#include <cstddef>

// ---------------------------------------------------------------------------
constexpr int H_  = 96;
constexpr int G_  = 288;
constexpr int T_  = 239;
constexpr int B_  = 4096;
constexpr int NB_ = 32;

constexpr int HP2 = 104;   // bf16 row pitch for ldmatrix tiles (16B-mult, conflict-ok)
constexpr int GHP = 297;   // f32 gh pitch (odd -> conflict-free column writes)

constexpr int KIN  = 512;
constexpr int NFC  = 384;
constexpr int NFCP = 385;
constexpr int KC   = 64;
constexpr int HPf  = 33;

constexpr size_t SZ_SEQ = (size_t)T_ * B_ * H_;
constexpr size_t SZ_GI  = (size_t)T_ * B_ * G_;
constexpr size_t SZ_H0  = (size_t)B_ * NFC;

__device__ float g_bufA[SZ_SEQ];
__device__ float g_bufB[SZ_SEQ];
__device__ float g_gi  [SZ_GI];
__device__ float g_h0  [SZ_H0];

// ---------------------------------------------------------------------------
__device__ __forceinline__ float sigf(float x)   { return 1.0f / (1.0f + __expf(-x)); }
__device__ __forceinline__ float tanh_f(float x) { return 2.0f / (1.0f + __expf(-2.0f * x)) - 1.0f; }

__device__ __forceinline__ uint32_t pack_bf16(__nv_bfloat16 a, __nv_bfloat16 b) {
    return (uint32_t)__bfloat16_as_ushort(a) | ((uint32_t)__bfloat16_as_ushort(b) << 16);
}
__device__ __forceinline__ void split2(float x, __nv_bfloat16& h, __nv_bfloat16& l) {
    h = __float2bfloat16(x);
    l = __float2bfloat16(x - __bfloat162float(h));
}

__device__ __forceinline__ void mma16816(float c[4], const uint32_t a[4], const uint32_t b[2]) {
    asm volatile(
        "mma.sync.aligned.m16n8k16.row.col.f32.bf16.bf16.f32 "
        "{%0,%1,%2,%3}, {%4,%5,%6,%7}, {%8,%9}, {%0,%1,%2,%3};"
        : "+f"(c[0]), "+f"(c[1]), "+f"(c[2]), "+f"(c[3])
        : "r"(a[0]), "r"(a[1]), "r"(a[2]), "r"(a[3]), "r"(b[0]), "r"(b[1]));
}
__device__ __forceinline__ void ldsm4(uint32_t r[4], uint32_t addr) {
    asm volatile("ldmatrix.sync.aligned.m8n8.x4.shared.b16 {%0,%1,%2,%3}, [%4];"
                 : "=r"(r[0]), "=r"(r[1]), "=r"(r[2]), "=r"(r[3]) : "r"(addr));
}

// Per-thread weight fragments for this warp's 32 output cols (4 n-tiles, 6 k-tiles)
struct BFrags { uint32_t hi[6][4][2]; uint32_t lo[6][4][2]; };

__device__ __forceinline__ void load_bfrags(const float* __restrict__ w, int lane, int ncb, BFrags& bf) {
#pragma unroll
    for (int kt = 0; kt < 6; ++kt)
#pragma unroll
        for (int nt = 0; nt < 4; ++nt) {
            const int g  = ncb + nt * 8 + (lane >> 2);
            const int k0 = kt * 16 + (lane & 3) * 2;
            const float* p = w + (size_t)g * H_ + k0;
            float w0 = p[0], w1 = p[1], w2 = p[8], w3 = p[9];
            __nv_bfloat16 h0, h1, h2, h3, l0, l1, l2, l3;
            split2(w0, h0, l0); split2(w1, h1, l1);
            split2(w2, h2, l2); split2(w3, h3, l3);
            bf.hi[kt][nt][0] = pack_bf16(h0, h1);
            bf.hi[kt][nt][1] = pack_bf16(h2, h3);
            bf.lo[kt][nt][0] = pack_bf16(l0, l1);
            bf.lo[kt][nt][1] = pack_bf16(l2, l3);
        }
}

// Split-bf16 GEMM: c[mt][nt] += Ahi*Bhi + Ahi*Blo + Alo*Bhi over 6 k-tiles.
// aHi/aLo: shared-space byte addresses (per-lane ldmatrix base for mt=0, kt=0).
__device__ __forceinline__ void gemm_step(uint32_t aHi, uint32_t aLo,
                                          const BFrags& bf, float c[2][4][4]) {
#pragma unroll
    for (int kt = 0; kt < 6; ++kt) {
        const uint32_t o = (uint32_t)(kt * 16 * 2);
        uint32_t ah0[4], ah1[4], al0[4], al1[4];
        ldsm4(ah0, aHi + o);
        ldsm4(ah1, aHi + o + 16 * HP2 * 2);
        ldsm4(al0, aLo + o);
        ldsm4(al1, aLo + o + 16 * HP2 * 2);
#pragma unroll
        for (int nt = 0; nt < 4; ++nt) {
            mma16816(c[0][nt], ah0, bf.hi[kt][nt]);
            mma16816(c[0][nt], ah0, bf.lo[kt][nt]);
            mma16816(c[0][nt], al0, bf.hi[kt][nt]);
            mma16816(c[1][nt], ah1, bf.hi[kt][nt]);
            mma16816(c[1][nt], ah1, bf.lo[kt][nt]);
            mma16816(c[1][nt], al1, bf.hi[kt][nt]);
        }
    }
}

// ---------------------------------------------------------------------------
// GRU scan, tensor-core version. One block = 32 batch rows, 288 threads.
// ---------------------------------------------------------------------------
template <bool HAS_GI>
__global__ void __launch_bounds__(288, 1)
scan_mma(const float* __restrict__ w_hh, const float* __restrict__ b_hh,
         const float* __restrict__ b_ih, const float* __restrict__ h0,
         const float* __restrict__ gi, float* __restrict__ outp)
{
    extern __shared__ char smraw[];
    float* gh = (float*)smraw;                              // [32][GHP]
    float* hf = gh + 32 * GHP;                              // [32][96] fp32 h
    __nv_bfloat16* hhi = (__nv_bfloat16*)(hf + 32 * 96);    // [32][HP2]
    __nv_bfloat16* hlo = hhi + 32 * HP2;                    // [32][HP2]

    const int tid  = threadIdx.x;
    const int lane = tid & 31;
    const int wid  = tid >> 5;      // 0..8
    const int ncb  = wid * 32;      // warp col base in [0,288)
    const int b0   = blockIdx.x * NB_;

    BFrags bf;
    load_bfrags(w_hh, lane, ncb, bf);

    float bhv[4][2];
#pragma unroll
    for (int nt = 0; nt < 4; ++nt) {
        const int col = ncb + nt * 8 + 2 * (lane & 3);
        bhv[nt][0] = b_hh[col];
        bhv[nt][1] = b_hh[col + 1];
    }

    // elementwise mapping: j fixed per thread, rows r = r0 + 3i
    const int j  = tid % 96;
    const int r0 = tid / 96;
    const float bi0 = b_ih[j], bi1 = b_ih[j + 96], bi2 = b_ih[j + 192];

    // init h state
#pragma unroll
    for (int i = 0; i < 11; ++i) {
        const int r = r0 + 3 * i;
        if (r < 32) {
            const float v = h0[(size_t)(b0 + r) * H_ + j];
            hf[r * 96 + j] = v;
            __nv_bfloat16 h, l; split2(v, h, l);
            hhi[r * HP2 + j] = h; hlo[r * HP2 + j] = l;
        }
    }
    __syncthreads();

    // ldmatrix per-lane addresses (mt=0, kt=0 base)
    const int arow = (lane & 7) + ((lane >> 3) & 1) * 8;
    const int acol = ((lane >> 4) & 1) * 8;
    const uint32_t aHi = (uint32_t)__cvta_generic_to_shared(hhi) + (uint32_t)((arow * HP2 + acol) * 2);
    const uint32_t aLo = (uint32_t)__cvta_generic_to_shared(hlo) + (uint32_t)((arow * HP2 + acol) * 2);

    const int crow = lane >> 2;
    const int ccol = ncb + 2 * (lane & 3);

    for (int t = 0; t < T_; ++t) {
        // prefetch gi for this step (hidden under the GEMM)
        float gv0[11], gv1[11], gv2[11];
        if (HAS_GI) {
            const float* gp = gi + ((size_t)t * B_ + b0) * G_;
#pragma unroll
            for (int i = 0; i < 11; ++i) {
                const int r = r0 + 3 * i;
                if (r < 32) {
                    const float* q = gp + (size_t)r * G_ + j;
                    gv0[i] = q[0]; gv1[i] = q[96]; gv2[i] = q[192];
                }
            }
        }

        float c[2][4][4];
#pragma unroll
        for (int mt = 0; mt < 2; ++mt)
#pragma unroll
            for (int nt = 0; nt < 4; ++nt)
#pragma unroll
                for (int q = 0; q < 4; ++q) c[mt][nt][q] = 0.f;

        gemm_step(aHi, aLo, bf, c);

        // gh = h @ whT + bh (bias folded here)
#pragma unroll
        for (int mt = 0; mt < 2; ++mt)
#pragma unroll
            for (int nt = 0; nt < 4; ++nt) {
                const int rowa = mt * 16 + crow;
                const int col  = ccol + nt * 8;
                gh[rowa * GHP + col]           = c[mt][nt][0] + bhv[nt][0];
                gh[rowa * GHP + col + 1]       = c[mt][nt][1] + bhv[nt][1];
                gh[(rowa + 8) * GHP + col]     = c[mt][nt][2] + bhv[nt][0];
                gh[(rowa + 8) * GHP + col + 1] = c[mt][nt][3] + bhv[nt][1];
            }
        __syncthreads();

        float* op = outp + ((size_t)t * B_ + b0) * H_;
#pragma unroll
        for (int i = 0; i < 11; ++i) {
            const int r = r0 + 3 * i;
            if (r < 32) {
                const float g0 = (HAS_GI ? gv0[i] : bi0) + gh[r * GHP + j];
                const float g1 = (HAS_GI ? gv1[i] : bi1) + gh[r * GHP + j + 96];
                const float hn = gh[r * GHP + j + 192];
                const float rg = sigf(g0);
                const float zg = sigf(g1);
                const float ng = tanh_f((HAS_GI ? gv2[i] : bi2) + rg * hn);
                const float hold = hf[r * 96 + j];
                const float hnew = ng + zg * (hold - ng);
                hf[r * 96 + j] = hnew;
                op[(size_t)r * H_ + j] = hnew;
                __nv_bfloat16 h, l; split2(hnew, h, l);
                hhi[r * HP2 + j] = h; hlo[r * HP2 + j] = l;
            }
        }
        __syncthreads();
    }
}

// ---------------------------------------------------------------------------
// gi = x @ w_ih^T + b_ih over all T*B rows (tensor-core, persistent blocks)
// ---------------------------------------------------------------------------
__global__ void __launch_bounds__(288, 1)
gi_mma(const float* __restrict__ w_ih, const float* __restrict__ b_ih,
       const float* __restrict__ x, float* __restrict__ gi)
{
    __shared__ __align__(16) __nv_bfloat16 xbuf[2 * 32 * HP2];
    __nv_bfloat16* xhi = xbuf;
    __nv_bfloat16* xlo = xbuf + 32 * HP2;

    const int tid  = threadIdx.x;
    const int lane = tid & 31;
    const int wid  = tid >> 5;
    const int ncb  = wid * 32;

    BFrags bf;
    load_bfrags(w_ih, lane, ncb, bf);

    float bv[4][2];
#pragma unroll
    for (int nt = 0; nt < 4; ++nt) {
        const int col = ncb + nt * 8 + 2 * (lane & 3);
        bv[nt][0] = b_ih[col];
        bv[nt][1] = b_ih[col + 1];
    }

    const int j  = tid % 96;
    const int r0 = tid / 96;

    const int arow = (lane & 7) + ((lane >> 3) & 1) * 8;
    const int acol = ((lane >> 4) & 1) * 8;
    const uint32_t aHi = (uint32_t)__cvta_generic_to_shared(xhi) + (uint32_t)((arow * HP2 + acol) * 2);
    const uint32_t aLo = (uint32_t)__cvta_generic_to_shared(xlo) + (uint32_t)((arow * HP2 + acol) * 2);

    const int crow = lane >> 2;
    const int ccol = ncb + 2 * (lane & 3);

    const int ntiles = T_ * B_ / NB_;
    for (int tile = blockIdx.x; tile < ntiles; tile += gridDim.x) {
        const size_t row0 = (size_t)tile * NB_;
#pragma unroll
        for (int i = 0; i < 11; ++i) {
            const int r = r0 + 3 * i;
            if (r < 32) {
                const float v = x[(row0 + r) * H_ + j];
                __nv_bfloat16 h, l; split2(v, h, l);
                xhi[r * HP2 + j] = h; xlo[r * HP2 + j] = l;
            }
        }
        __syncthreads();

        float c[2][4][4];
#pragma unroll
        for (int mt = 0; mt < 2; ++mt)
#pragma unroll
            for (int nt = 0; nt < 4; ++nt)
#pragma unroll
                for (int q = 0; q < 4; ++q) c[mt][nt][q] = 0.f;

        gemm_step(aHi, aLo, bf, c);

#pragma unroll
        for (int mt = 0; mt < 2; ++mt)
#pragma unroll
            for (int nt = 0; nt < 4; ++nt) {
                const size_t ra = row0 + mt * 16 + crow;
                const int col   = ccol + nt * 8;
                float2 v01 = make_float2(c[mt][nt][0] + bv[nt][0], c[mt][nt][1] + bv[nt][1]);
                float2 v23 = make_float2(c[mt][nt][2] + bv[nt][0], c[mt][nt][3] + bv[nt][1]);
                *(float2*)(gi + ra * G_ + col)       = v01;
                *(float2*)(gi + (ra + 8) * G_ + col) = v23;
            }
        __syncthreads();
    }
}

// ---------------------------------------------------------------------------
// fc1 (fp32, tiny) — unchanged from round 1
// ---------------------------------------------------------------------------
__global__ void __launch_bounds__(256, 1)
fc1_kernel(const float* __restrict__ z, const float* __restrict__ c,
           const float* __restrict__ w, const float* __restrict__ bias,
           float* __restrict__ h0out)
{
    extern __shared__ float sm[];
    float* wc_s = sm;
    float* xc_s = wc_s + KC * NFCP;

    const int tid = threadIdx.x;
    const int cx  = tid & 31;
    const int ry  = tid >> 5;
    const int b0  = blockIdx.x * NB_;

    float acc[4][12];
#pragma unroll
    for (int m = 0; m < 4; ++m)
#pragma unroll
        for (int i = 0; i < 12; ++i) acc[m][i] = 0.f;

    for (int kc = 0; kc < KIN; kc += KC) {
        for (int idx = tid; idx < NFC * KC; idx += 256) {
            int g = idx / KC, kk = idx - g * KC;
            wc_s[kk * NFCP + g] = w[(size_t)g * KIN + kc + kk];
        }
        for (int idx = tid; idx < NB_ * KC; idx += 256) {
            int r = idx / KC, kk = idx - r * KC;
            int k = kc + kk;
            float v = (k < 256) ? z[(size_t)(b0 + r) * 256 + k]
                                : c[(size_t)(b0 + r) * 256 + (k - 256)];
            xc_s[kk * HPf + r] = v;
        }
        __syncthreads();
#pragma unroll 4
        for (int kk = 0; kk < KC; ++kk) {
            const float a0 = xc_s[kk * HPf + ry +  0];
            const float a1 = xc_s[kk * HPf + ry +  8];
            const float a2 = xc_s[kk * HPf + ry + 16];
            const float a3 = xc_s[kk * HPf + ry + 24];
            const float* wr = wc_s + kk * NFCP + cx;
#pragma unroll
            for (int i = 0; i < 12; ++i) {
                const float wv = wr[32 * i];
                acc[0][i] = fmaf(a0, wv, acc[0][i]);
                acc[1][i] = fmaf(a1, wv, acc[1][i]);
                acc[2][i] = fmaf(a2, wv, acc[2][i]);
                acc[3][i] = fmaf(a3, wv, acc[3][i]);
            }
        }
        __syncthreads();
    }

#pragma unroll
    for (int m = 0; m < 4; ++m) {
        const int r = b0 + ry + 8 * m;
#pragma unroll
        for (int i = 0; i < 12; ++i) {
            const int g = cx + 32 * i;
            float v = acc[m][i] + bias[g];
            v = (v >= 0.f) ? v : 0.2f * v;
            h0out[(size_t)r * NFC + g] = v;
        }
    }
}

// ---------------------------------------------------------------------------
// [T,B,H] -> [B,H,T] transpose
// ---------------------------------------------------------------------------
__global__ void transpose_kernel(const float* __restrict__ in, float* __restrict__ outp)
{
    __shared__ float tile[32][33];
    const int b  = blockIdx.z;
    const int j0 = blockIdx.y * 32;
    const int t0 = blockIdx.x * 32;
    const int tx = threadIdx.x, ty = threadIdx.y;

#pragma unroll
    for (int yy = ty; yy < 32; yy += 8) {
        const int t = t0 + yy;
        if (t < T_) tile[yy][tx] = in[((size_t)t * B_ + b) * H_ + j0 + tx];
    }
    __syncthreads();
#pragma unroll
    for (int yy = ty; yy < 32; yy += 8) {
        const int t = t0 + tx;
        const int j = j0 + yy;
        if (t < T_) outp[((size_t)b * H_ + j) * T_ + t] = tile[tx][yy];
    }
}

// ---------------------------------------------------------------------------
extern "C" void kernel_launch(void* const* d_in, const int* in_sizes, int n_in,
                              void* d_out, int out_size)
{
    const float* z     = (const float*)d_in[0];
    const float* c     = (const float*)d_in[1];
    const float* fc1_w = (const float*)d_in[2];
    const float* fc1_b = (const float*)d_in[3];
    const float* w_ih  = (const float*)d_in[4];
    const float* w_hh  = (const float*)d_in[5];
    const float* b_ih  = (const float*)d_in[6];
    const float* b_hh  = (const float*)d_in[7];
    float* out = (float*)d_out;

    float *bufA, *bufB, *giBuf, *h0Buf;
    cudaGetSymbolAddress((void**)&bufA,  g_bufA);
    cudaGetSymbolAddress((void**)&bufB,  g_bufB);
    cudaGetSymbolAddress((void**)&giBuf, g_gi);
    cudaGetSymbolAddress((void**)&h0Buf, g_h0);

    const size_t scanSm = (size_t)(32 * GHP + 32 * 96) * sizeof(float)
                        + (size_t)(2 * 32 * HP2) * sizeof(__nv_bfloat16);   // ~63.6 KB
    const size_t fcSm   = (size_t)(KC * NFCP + KC * HPf) * sizeof(float);

    cudaFuncSetAttribute(scan_mma<false>, cudaFuncAttributeMaxDynamicSharedMemorySize, (int)scanSm);
    cudaFuncSetAttribute(scan_mma<true>,  cudaFuncAttributeMaxDynamicSharedMemorySize, (int)scanSm);
    cudaFuncSetAttribute(fc1_kernel,      cudaFuncAttributeMaxDynamicSharedMemorySize, (int)fcSm);

    const int nblk = B_ / NB_;  // 128

    fc1_kernel<<<nblk, 256, fcSm>>>(z, c, fc1_w, fc1_b, h0Buf);

    // layer 0 (input zeros: gi == b_ih)
    scan_mma<false><<<nblk, 288, scanSm>>>(w_hh, b_hh, b_ih, h0Buf, nullptr, bufA);

    // layers 1..3
    const float* srcs[3] = {bufA, bufB, bufA};
    float*       dsts[3] = {bufB, bufA, bufB};
    for (int l = 1; l < 4; ++l) {
        const size_t wo = (size_t)l * G_ * H_;
        const size_t bo = (size_t)l * G_;
        gi_mma<<<148, 288>>>(w_ih + wo, b_ih + bo, srcs[l - 1], giBuf);
        scan_mma<true><<<nblk, 288, scanSm>>>(w_hh + wo, b_hh + bo, b_ih + bo,
                                              h0Buf + (size_t)l * B_ * H_, giBuf, dsts[l - 1]);
    }

    transpose_kernel<<<dim3(8, 3, B_), dim3(32, 8)>>>(bufB, out);
}

// round 4
// speedup vs baseline: 1.3363x; 1.3363x over previous
#include <cuda_runtime.h>
#include <cuda_bf16.h>
#include <cstdint>
#include <cstddef>

// ---------------------------------------------------------------------------
constexpr int H_  = 96;
constexpr int G_  = 288;
constexpr int T_  = 239;
constexpr int B_  = 4096;
constexpr int NB_ = 32;

constexpr int HP2 = 104;   // bf16 row pitch for ldmatrix tiles

constexpr int KIN  = 512;
constexpr int NFC  = 384;
constexpr int NFCP = 385;
constexpr int KC   = 64;
constexpr int HPf  = 33;

constexpr size_t SZ_SEQ = (size_t)T_ * B_ * H_;
constexpr size_t SZ_GI  = (size_t)T_ * B_ * G_;
constexpr size_t SZ_H0  = (size_t)B_ * NFC;

__device__ float g_bufA[SZ_SEQ];
__device__ float g_bufB[SZ_SEQ];
__device__ float g_gi  [SZ_GI];
__device__ float g_h0  [SZ_H0];

// ---------------------------------------------------------------------------
__device__ __forceinline__ float sigf(float x)   { return 1.0f / (1.0f + __expf(-x)); }
__device__ __forceinline__ float tanh_f(float x) { return 2.0f / (1.0f + __expf(-2.0f * x)) - 1.0f; }

__device__ __forceinline__ uint32_t pack_bf16(__nv_bfloat16 a, __nv_bfloat16 b) {
    return (uint32_t)__bfloat16_as_ushort(a) | ((uint32_t)__bfloat16_as_ushort(b) << 16);
}
__device__ __forceinline__ void split2(float x, __nv_bfloat16& h, __nv_bfloat16& l) {
    h = __float2bfloat16(x);
    l = __float2bfloat16(x - __bfloat162float(h));
}

__device__ __forceinline__ void mma16816(float c[4], const uint32_t a[4], const uint32_t b[2]) {
    asm volatile(
        "mma.sync.aligned.m16n8k16.row.col.f32.bf16.bf16.f32 "
        "{%0,%1,%2,%3}, {%4,%5,%6,%7}, {%8,%9}, {%0,%1,%2,%3};"
        : "+f"(c[0]), "+f"(c[1]), "+f"(c[2]), "+f"(c[3])
        : "r"(a[0]), "r"(a[1]), "r"(a[2]), "r"(a[3]), "r"(b[0]), "r"(b[1]));
}
__device__ __forceinline__ void ldsm4(uint32_t r[4], uint32_t addr) {
    asm volatile("ldmatrix.sync.aligned.m8n8.x4.shared.b16 {%0,%1,%2,%3}, [%4];"
                 : "=r"(r[0]), "=r"(r[1]), "=r"(r[2]), "=r"(r[3]) : "r"(addr));
}

// ---------------------------------------------------------------------------
// GRU scan v2: gate-aligned warps, register elementwise, 1 barrier/step.
// 384 threads = 12 warps; warp w owns j in [8w, 8w+8), gates at +0,+96,+192.
// ---------------------------------------------------------------------------
template <bool HAS_GI>
__global__ void __launch_bounds__(384, 1)
scan2(const float* __restrict__ w_hh, const float* __restrict__ b_hh,
      const float* __restrict__ b_ih, const float* __restrict__ h0,
      const float* __restrict__ gi, float* __restrict__ outp)
{
    // [phase][hi/lo][32*HP2]
    __shared__ __align__(16) __nv_bfloat16 hb[2][2][32 * HP2];

    const int tid  = threadIdx.x;
    const int lane = tid & 31;
    const int w    = tid >> 5;          // 0..11
    const int b0   = blockIdx.x * NB_;

    // --- weight fragments (r,z,n gate tiles for this warp's 8 j-cols) ---
    uint32_t bhi[6][3][2], blo[6][3][2];
#pragma unroll
    for (int kt = 0; kt < 6; ++kt)
#pragma unroll
        for (int nt = 0; nt < 3; ++nt) {
            const int g  = nt * 96 + 8 * w + (lane >> 2);
            const int k0 = kt * 16 + (lane & 3) * 2;
            const float* p = w_hh + (size_t)g * H_ + k0;
            float w0 = p[0], w1 = p[1], w2 = p[8], w3 = p[9];
            __nv_bfloat16 h0b, h1b, h2b, h3b, l0b, l1b, l2b, l3b;
            split2(w0, h0b, l0b); split2(w1, h1b, l1b);
            split2(w2, h2b, l2b); split2(w3, h3b, l3b);
            bhi[kt][nt][0] = pack_bf16(h0b, h1b);
            bhi[kt][nt][1] = pack_bf16(h2b, h3b);
            blo[kt][nt][0] = pack_bf16(l0b, l1b);
            blo[kt][nt][1] = pack_bf16(l2b, l3b);
        }

    const int crow = lane >> 2;
    const int jc   = 8 * w + 2 * (lane & 3);

    float bh[3][2], bi[3][2];
#pragma unroll
    for (int g = 0; g < 3; ++g) {
        bh[g][0] = b_hh[g * 96 + jc];
        bh[g][1] = b_hh[g * 96 + jc + 1];
        bi[g][0] = b_ih[g * 96 + jc];
        bi[g][1] = b_ih[g * 96 + jc + 1];
    }

    // --- init h state: registers + bf16 split buffers (phase 0) ---
    float hold[2][4];   // [mt][rh*2+col]
#pragma unroll
    for (int mt = 0; mt < 2; ++mt)
#pragma unroll
        for (int rh = 0; rh < 2; ++rh) {
            const int row = mt * 16 + crow + rh * 8;
            const float2 v = *(const float2*)&h0[(size_t)(b0 + row) * H_ + jc];
            hold[mt][rh * 2]     = v.x;
            hold[mt][rh * 2 + 1] = v.y;
            __nv_bfloat16 hx, lx, hy, ly;
            split2(v.x, hx, lx); split2(v.y, hy, ly);
            *(uint32_t*)&hb[0][0][row * HP2 + jc] = pack_bf16(hx, hy);
            *(uint32_t*)&hb[0][1][row * HP2 + jc] = pack_bf16(lx, ly);
        }
    __syncthreads();

    // ldmatrix per-lane offsets
    const int arow = (lane & 7) + ((lane >> 3) & 1) * 8;
    const int acol = ((lane >> 4) & 1) * 8;
    const uint32_t sbase = (uint32_t)__cvta_generic_to_shared(&hb[0][0][0]);
    const uint32_t lofs  = (uint32_t)((arow * HP2 + acol) * 2);
    constexpr uint32_t BUFB = (uint32_t)(32 * HP2 * 2);   // bytes per buffer

    for (int t = 0; t < T_; ++t) {
        const int p = t & 1;

        // prefetch gi for this step (consumed after the MMA chain)
        float2 gv[2][2][3];
        if (HAS_GI) {
            const float* gp = gi + ((size_t)t * B_ + b0) * G_;
#pragma unroll
            for (int mt = 0; mt < 2; ++mt)
#pragma unroll
                for (int rh = 0; rh < 2; ++rh) {
                    const size_t ro = (size_t)(mt * 16 + crow + rh * 8) * G_;
#pragma unroll
                    for (int g = 0; g < 3; ++g)
                        gv[mt][rh][g] = *(const float2*)&gp[ro + g * 96 + jc];
                }
        }

        float c[2][3][4];
#pragma unroll
        for (int mt = 0; mt < 2; ++mt)
#pragma unroll
            for (int nt = 0; nt < 3; ++nt)
#pragma unroll
                for (int q = 0; q < 4; ++q) c[mt][nt][q] = 0.f;

        const uint32_t aH = sbase + (uint32_t)(p * 2) * BUFB + lofs;
        const uint32_t aL = aH + BUFB;

#pragma unroll
        for (int kt = 0; kt < 6; ++kt) {
            const uint32_t o = (uint32_t)(kt * 32);
            uint32_t ah0[4], ah1[4], al0[4], al1[4];
            ldsm4(ah0, aH + o);
            ldsm4(ah1, aH + o + 16 * HP2 * 2);
            ldsm4(al0, aL + o);
            ldsm4(al1, aL + o + 16 * HP2 * 2);
            // term 1: Ahi*Bhi
#pragma unroll
            for (int nt = 0; nt < 3; ++nt) {
                mma16816(c[0][nt], ah0, bhi[kt][nt]);
                mma16816(c[1][nt], ah1, bhi[kt][nt]);
            }
            // term 2: Ahi*Blo
#pragma unroll
            for (int nt = 0; nt < 3; ++nt) {
                mma16816(c[0][nt], ah0, blo[kt][nt]);
                mma16816(c[1][nt], ah1, blo[kt][nt]);
            }
            // term 3: Alo*Bhi
#pragma unroll
            for (int nt = 0; nt < 3; ++nt) {
                mma16816(c[0][nt], al0, bhi[kt][nt]);
                mma16816(c[1][nt], al1, bhi[kt][nt]);
            }
        }

        // register elementwise: r,z,n all live in this thread's fragments
        float* op = outp + ((size_t)t * B_ + b0) * H_;
        const int pn = p ^ 1;
#pragma unroll
        for (int mt = 0; mt < 2; ++mt)
#pragma unroll
            for (int rh = 0; rh < 2; ++rh) {
                const int row = mt * 16 + crow + rh * 8;
                float hn2[2];
#pragma unroll
                for (int col = 0; col < 2; ++col) {
                    const int q = rh * 2 + col;
                    const float ir = HAS_GI ? ((col == 0) ? gv[mt][rh][0].x : gv[mt][rh][0].y) : bi[0][col];
                    const float iz = HAS_GI ? ((col == 0) ? gv[mt][rh][1].x : gv[mt][rh][1].y) : bi[1][col];
                    const float in_ = HAS_GI ? ((col == 0) ? gv[mt][rh][2].x : gv[mt][rh][2].y) : bi[2][col];
                    const float rg = sigf(ir + c[mt][0][q] + bh[0][col]);
                    const float zg = sigf(iz + c[mt][1][q] + bh[1][col]);
                    const float ng = tanh_f(in_ + rg * (c[mt][2][q] + bh[2][col]));
                    const float hv = ng + zg * (hold[mt][q] - ng);
                    hold[mt][q] = hv;
                    hn2[col] = hv;
                }
                // write output + split state into next-phase buffers
                *(float2*)&op[(size_t)row * H_ + jc] = make_float2(hn2[0], hn2[1]);
                __nv_bfloat16 hx, lx, hy, ly;
                split2(hn2[0], hx, lx); split2(hn2[1], hy, ly);
                *(uint32_t*)&hb[pn][0][row * HP2 + jc] = pack_bf16(hx, hy);
                *(uint32_t*)&hb[pn][1][row * HP2 + jc] = pack_bf16(lx, ly);
            }
        __syncthreads();
    }
}

// ---------------------------------------------------------------------------
// gi = x @ w_ih^T + b_ih  (tensor-core, persistent blocks; round-2 proven)
// ---------------------------------------------------------------------------
struct BFrags { uint32_t hi[6][4][2]; uint32_t lo[6][4][2]; };

__device__ __forceinline__ void load_bfrags(const float* __restrict__ w, int lane, int ncb, BFrags& bf) {
#pragma unroll
    for (int kt = 0; kt < 6; ++kt)
#pragma unroll
        for (int nt = 0; nt < 4; ++nt) {
            const int g  = ncb + nt * 8 + (lane >> 2);
            const int k0 = kt * 16 + (lane & 3) * 2;
            const float* p = w + (size_t)g * H_ + k0;
            float w0 = p[0], w1 = p[1], w2 = p[8], w3 = p[9];
            __nv_bfloat16 h0, h1, h2, h3, l0, l1, l2, l3;
            split2(w0, h0, l0); split2(w1, h1, l1);
            split2(w2, h2, l2); split2(w3, h3, l3);
            bf.hi[kt][nt][0] = pack_bf16(h0, h1);
            bf.hi[kt][nt][1] = pack_bf16(h2, h3);
            bf.lo[kt][nt][0] = pack_bf16(l0, l1);
            bf.lo[kt][nt][1] = pack_bf16(l2, l3);
        }
}

__global__ void __launch_bounds__(288, 1)
gi_mma(const float* __restrict__ w_ih, const float* __restrict__ b_ih,
       const float* __restrict__ x, float* __restrict__ gi)
{
    __shared__ __align__(16) __nv_bfloat16 xbuf[2 * 32 * HP2];
    __nv_bfloat16* xhi = xbuf;
    __nv_bfloat16* xlo = xbuf + 32 * HP2;

    const int tid  = threadIdx.x;
    const int lane = tid & 31;
    const int wid  = tid >> 5;
    const int ncb  = wid * 32;

    BFrags bf;
    load_bfrags(w_ih, lane, ncb, bf);

    float bv[4][2];
#pragma unroll
    for (int nt = 0; nt < 4; ++nt) {
        const int col = ncb + nt * 8 + 2 * (lane & 3);
        bv[nt][0] = b_ih[col];
        bv[nt][1] = b_ih[col + 1];
    }

    const int j  = tid % 96;
    const int r0 = tid / 96;

    const int arow = (lane & 7) + ((lane >> 3) & 1) * 8;
    const int acol = ((lane >> 4) & 1) * 8;
    const uint32_t aHi = (uint32_t)__cvta_generic_to_shared(xhi) + (uint32_t)((arow * HP2 + acol) * 2);
    const uint32_t aLo = (uint32_t)__cvta_generic_to_shared(xlo) + (uint32_t)((arow * HP2 + acol) * 2);

    const int crow = lane >> 2;
    const int ccol = ncb + 2 * (lane & 3);

    const int ntiles = T_ * B_ / NB_;
    for (int tile = blockIdx.x; tile < ntiles; tile += gridDim.x) {
        const size_t row0 = (size_t)tile * NB_;
#pragma unroll
        for (int i = 0; i < 11; ++i) {
            const int r = r0 + 3 * i;
            if (r < 32) {
                const float v = x[(row0 + r) * H_ + j];
                __nv_bfloat16 h, l; split2(v, h, l);
                xhi[r * HP2 + j] = h; xlo[r * HP2 + j] = l;
            }
        }
        __syncthreads();

        float c[2][4][4];
#pragma unroll
        for (int mt = 0; mt < 2; ++mt)
#pragma unroll
            for (int nt = 0; nt < 4; ++nt)
#pragma unroll
                for (int q = 0; q < 4; ++q) c[mt][nt][q] = 0.f;

#pragma unroll
        for (int kt = 0; kt < 6; ++kt) {
            const uint32_t o = (uint32_t)(kt * 32);
            uint32_t ah0[4], ah1[4], al0[4], al1[4];
            ldsm4(ah0, aHi + o);
            ldsm4(ah1, aHi + o + 16 * HP2 * 2);
            ldsm4(al0, aLo + o);
            ldsm4(al1, aLo + o + 16 * HP2 * 2);
#pragma unroll
            for (int nt = 0; nt < 4; ++nt) {
                mma16816(c[0][nt], ah0, bf.hi[kt][nt]);
                mma16816(c[1][nt], ah1, bf.hi[kt][nt]);
            }
#pragma unroll
            for (int nt = 0; nt < 4; ++nt) {
                mma16816(c[0][nt], ah0, bf.lo[kt][nt]);
                mma16816(c[1][nt], ah1, bf.lo[kt][nt]);
            }
#pragma unroll
            for (int nt = 0; nt < 4; ++nt) {
                mma16816(c[0][nt], al0, bf.hi[kt][nt]);
                mma16816(c[1][nt], al1, bf.hi[kt][nt]);
            }
        }

#pragma unroll
        for (int mt = 0; mt < 2; ++mt)
#pragma unroll
            for (int nt = 0; nt < 4; ++nt) {
                const size_t ra = row0 + mt * 16 + crow;
                const int col   = ccol + nt * 8;
                float2 v01 = make_float2(c[mt][nt][0] + bv[nt][0], c[mt][nt][1] + bv[nt][1]);
                float2 v23 = make_float2(c[mt][nt][2] + bv[nt][0], c[mt][nt][3] + bv[nt][1]);
                *(float2*)(gi + ra * G_ + col)       = v01;
                *(float2*)(gi + (ra + 8) * G_ + col) = v23;
            }
        __syncthreads();
    }
}

// ---------------------------------------------------------------------------
// fc1 (fp32, tiny)
// ---------------------------------------------------------------------------
__global__ void __launch_bounds__(256, 1)
fc1_kernel(const float* __restrict__ z, const float* __restrict__ c,
           const float* __restrict__ w, const float* __restrict__ bias,
           float* __restrict__ h0out)
{
    extern __shared__ float sm[];
    float* wc_s = sm;
    float* xc_s = wc_s + KC * NFCP;

    const int tid = threadIdx.x;
    const int cx  = tid & 31;
    const int ry  = tid >> 5;
    const int b0  = blockIdx.x * NB_;

    float acc[4][12];
#pragma unroll
    for (int m = 0; m < 4; ++m)
#pragma unroll
        for (int i = 0; i < 12; ++i) acc[m][i] = 0.f;

    for (int kc = 0; kc < KIN; kc += KC) {
        for (int idx = tid; idx < NFC * KC; idx += 256) {
            int g = idx / KC, kk = idx - g * KC;
            wc_s[kk * NFCP + g] = w[(size_t)g * KIN + kc + kk];
        }
        for (int idx = tid; idx < NB_ * KC; idx += 256) {
            int r = idx / KC, kk = idx - r * KC;
            int k = kc + kk;
            float v = (k < 256) ? z[(size_t)(b0 + r) * 256 + k]
                                : c[(size_t)(b0 + r) * 256 + (k - 256)];
            xc_s[kk * HPf + r] = v;
        }
        __syncthreads();
#pragma unroll 4
        for (int kk = 0; kk < KC; ++kk) {
            const float a0 = xc_s[kk * HPf + ry +  0];
            const float a1 = xc_s[kk * HPf + ry +  8];
            const float a2 = xc_s[kk * HPf + ry + 16];
            const float a3 = xc_s[kk * HPf + ry + 24];
            const float* wr = wc_s + kk * NFCP + cx;
#pragma unroll
            for (int i = 0; i < 12; ++i) {
                const float wv = wr[32 * i];
                acc[0][i] = fmaf(a0, wv, acc[0][i]);
                acc[1][i] = fmaf(a1, wv, acc[1][i]);
                acc[2][i] = fmaf(a2, wv, acc[2][i]);
                acc[3][i] = fmaf(a3, wv, acc[3][i]);
            }
        }
        __syncthreads();
    }

#pragma unroll
    for (int m = 0; m < 4; ++m) {
        const int r = b0 + ry + 8 * m;
#pragma unroll
        for (int i = 0; i < 12; ++i) {
            const int g = cx + 32 * i;
            float v = acc[m][i] + bias[g];
            v = (v >= 0.f) ? v : 0.2f * v;
            h0out[(size_t)r * NFC + g] = v;
        }
    }
}

// ---------------------------------------------------------------------------
// [T,B,H] -> [B,H,T] transpose
// ---------------------------------------------------------------------------
__global__ void transpose_kernel(const float* __restrict__ in, float* __restrict__ outp)
{
    __shared__ float tile[32][33];
    const int b  = blockIdx.z;
    const int j0 = blockIdx.y * 32;
    const int t0 = blockIdx.x * 32;
    const int tx = threadIdx.x, ty = threadIdx.y;

#pragma unroll
    for (int yy = ty; yy < 32; yy += 8) {
        const int t = t0 + yy;
        if (t < T_) tile[yy][tx] = in[((size_t)t * B_ + b) * H_ + j0 + tx];
    }
    __syncthreads();
#pragma unroll
    for (int yy = ty; yy < 32; yy += 8) {
        const int t = t0 + tx;
        const int j = j0 + yy;
        if (t < T_) outp[((size_t)b * H_ + j) * T_ + t] = tile[tx][yy];
    }
}

// ---------------------------------------------------------------------------
extern "C" void kernel_launch(void* const* d_in, const int* in_sizes, int n_in,
                              void* d_out, int out_size)
{
    const float* z     = (const float*)d_in[0];
    const float* c     = (const float*)d_in[1];
    const float* fc1_w = (const float*)d_in[2];
    const float* fc1_b = (const float*)d_in[3];
    const float* w_ih  = (const float*)d_in[4];
    const float* w_hh  = (const float*)d_in[5];
    const float* b_ih  = (const float*)d_in[6];
    const float* b_hh  = (const float*)d_in[7];
    float* out = (float*)d_out;

    float *bufA, *bufB, *giBuf, *h0Buf;
    cudaGetSymbolAddress((void**)&bufA,  g_bufA);
    cudaGetSymbolAddress((void**)&bufB,  g_bufB);
    cudaGetSymbolAddress((void**)&giBuf, g_gi);
    cudaGetSymbolAddress((void**)&h0Buf, g_h0);

    const size_t fcSm = (size_t)(KC * NFCP + KC * HPf) * sizeof(float);
    cudaFuncSetAttribute(fc1_kernel, cudaFuncAttributeMaxDynamicSharedMemorySize, (int)fcSm);

    const int nblk = B_ / NB_;  // 128

    fc1_kernel<<<nblk, 256, fcSm>>>(z, c, fc1_w, fc1_b, h0Buf);

    // layer 0 (input zeros: gi == b_ih)
    scan2<false><<<nblk, 384>>>(w_hh, b_hh, b_ih, h0Buf, nullptr, bufA);

    // layers 1..3
    const float* srcs[3] = {bufA, bufB, bufA};
    float*       dsts[3] = {bufB, bufA, bufB};
    for (int l = 1; l < 4; ++l) {
        const size_t wo = (size_t)l * G_ * H_;
        const size_t bo = (size_t)l * G_;
        gi_mma<<<148, 288>>>(w_ih + wo, b_ih + bo, srcs[l - 1], giBuf);
        scan2<true><<<nblk, 384>>>(w_hh + wo, b_hh + bo, b_ih + bo,
                                   h0Buf + (size_t)l * B_ * H_, giBuf, dsts[l - 1]);
    }

    transpose_kernel<<<dim3(8, 3, B_), dim3(32, 8)>>>(bufB, out);
}

// round 5
// speedup vs baseline: 1.3374x; 1.0008x over previous
#include <cuda_runtime.h>
#include <cuda_bf16.h>
#include <cstdint>
#include <cstddef>

// ---------------------------------------------------------------------------
constexpr int H_  = 96;
constexpr int G_  = 288;
constexpr int T_  = 239;
constexpr int B_  = 4096;
constexpr int NB_ = 32;

constexpr int HP2 = 104;   // bf16 row pitch for ldmatrix tiles

constexpr int KIN  = 512;
constexpr int NFC  = 384;
constexpr int NFCP = 385;
constexpr int KC   = 64;
constexpr int HPf  = 33;

constexpr size_t SZ_SEQ = (size_t)T_ * B_ * H_;
constexpr size_t SZ_GI  = (size_t)T_ * B_ * G_;
constexpr size_t SZ_H0  = (size_t)B_ * NFC;

__device__ float g_bufA[SZ_SEQ];
__device__ float g_bufB[SZ_SEQ];
__device__ float g_gi  [SZ_GI];
__device__ float g_h0  [SZ_H0];

// ---------------------------------------------------------------------------
__device__ __forceinline__ float sigf(float x)   { return 1.0f / (1.0f + __expf(-x)); }
__device__ __forceinline__ float tanh_f(float x) { return 2.0f / (1.0f + __expf(-2.0f * x)) - 1.0f; }

__device__ __forceinline__ uint32_t pack_bf16(__nv_bfloat16 a, __nv_bfloat16 b) {
    return (uint32_t)__bfloat16_as_ushort(a) | ((uint32_t)__bfloat16_as_ushort(b) << 16);
}
__device__ __forceinline__ void split2(float x, __nv_bfloat16& h, __nv_bfloat16& l) {
    h = __float2bfloat16(x);
    l = __float2bfloat16(x - __bfloat162float(h));
}

__device__ __forceinline__ void mma16816(float c[4], const uint32_t a[4], const uint32_t b[2]) {
    asm volatile(
        "mma.sync.aligned.m16n8k16.row.col.f32.bf16.bf16.f32 "
        "{%0,%1,%2,%3}, {%4,%5,%6,%7}, {%8,%9}, {%0,%1,%2,%3};"
        : "+f"(c[0]), "+f"(c[1]), "+f"(c[2]), "+f"(c[3])
        : "r"(a[0]), "r"(a[1]), "r"(a[2]), "r"(a[3]), "r"(b[0]), "r"(b[1]));
}
__device__ __forceinline__ void ldsm4(uint32_t r[4], uint32_t addr) {
    asm volatile("ldmatrix.sync.aligned.m8n8.x4.shared.b16 {%0,%1,%2,%3}, [%4];"
                 : "=r"(r[0]), "=r"(r[1]), "=r"(r[2]), "=r"(r[3]) : "r"(addr));
}

// ---------------------------------------------------------------------------
// GRU scan v2: gate-aligned warps, register elementwise, 1 barrier/step.
// 384 threads = 12 warps; warp w owns j in [8w, 8w+8), gates at +0,+96,+192.
// ---------------------------------------------------------------------------
template <bool HAS_GI>
__global__ void __launch_bounds__(384, 1)
scan2(const float* __restrict__ w_hh, const float* __restrict__ b_hh,
      const float* __restrict__ b_ih, const float* __restrict__ h0,
      const float* __restrict__ gi, float* __restrict__ outp)
{
    // [phase][hi/lo][32*HP2]
    __shared__ __align__(16) __nv_bfloat16 hb[2][2][32 * HP2];

    const int tid  = threadIdx.x;
    const int lane = tid & 31;
    const int w    = tid >> 5;          // 0..11
    const int b0   = blockIdx.x * NB_;

    // --- weight fragments (r,z,n gate tiles for this warp's 8 j-cols) ---
    uint32_t bhi[6][3][2], blo[6][3][2];
#pragma unroll
    for (int kt = 0; kt < 6; ++kt)
#pragma unroll
        for (int nt = 0; nt < 3; ++nt) {
            const int g  = nt * 96 + 8 * w + (lane >> 2);
            const int k0 = kt * 16 + (lane & 3) * 2;
            const float* p = w_hh + (size_t)g * H_ + k0;
            float w0 = p[0], w1 = p[1], w2 = p[8], w3 = p[9];
            __nv_bfloat16 h0b, h1b, h2b, h3b, l0b, l1b, l2b, l3b;
            split2(w0, h0b, l0b); split2(w1, h1b, l1b);
            split2(w2, h2b, l2b); split2(w3, h3b, l3b);
            bhi[kt][nt][0] = pack_bf16(h0b, h1b);
            bhi[kt][nt][1] = pack_bf16(h2b, h3b);
            blo[kt][nt][0] = pack_bf16(l0b, l1b);
            blo[kt][nt][1] = pack_bf16(l2b, l3b);
        }

    const int crow = lane >> 2;
    const int jc   = 8 * w + 2 * (lane & 3);

    float bh[3][2], bi[3][2];
#pragma unroll
    for (int g = 0; g < 3; ++g) {
        bh[g][0] = b_hh[g * 96 + jc];
        bh[g][1] = b_hh[g * 96 + jc + 1];
        bi[g][0] = b_ih[g * 96 + jc];
        bi[g][1] = b_ih[g * 96 + jc + 1];
    }

    // --- init h state: registers + bf16 split buffers (phase 0) ---
    float hold[2][4];   // [mt][rh*2+col]
#pragma unroll
    for (int mt = 0; mt < 2; ++mt)
#pragma unroll
        for (int rh = 0; rh < 2; ++rh) {
            const int row = mt * 16 + crow + rh * 8;
            const float2 v = *(const float2*)&h0[(size_t)(b0 + row) * H_ + jc];
            hold[mt][rh * 2]     = v.x;
            hold[mt][rh * 2 + 1] = v.y;
            __nv_bfloat16 hx, lx, hy, ly;
            split2(v.x, hx, lx); split2(v.y, hy, ly);
            *(uint32_t*)&hb[0][0][row * HP2 + jc] = pack_bf16(hx, hy);
            *(uint32_t*)&hb[0][1][row * HP2 + jc] = pack_bf16(lx, ly);
        }
    __syncthreads();

    // ldmatrix per-lane offsets
    const int arow = (lane & 7) + ((lane >> 3) & 1) * 8;
    const int acol = ((lane >> 4) & 1) * 8;
    const uint32_t sbase = (uint32_t)__cvta_generic_to_shared(&hb[0][0][0]);
    const uint32_t lofs  = (uint32_t)((arow * HP2 + acol) * 2);
    constexpr uint32_t BUFB = (uint32_t)(32 * HP2 * 2);   // bytes per buffer

    for (int t = 0; t < T_; ++t) {
        const int p = t & 1;

        // prefetch gi for this step (consumed after the MMA chain)
        float2 gv[2][2][3];
        if (HAS_GI) {
            const float* gp = gi + ((size_t)t * B_ + b0) * G_;
#pragma unroll
            for (int mt = 0; mt < 2; ++mt)
#pragma unroll
                for (int rh = 0; rh < 2; ++rh) {
                    const size_t ro = (size_t)(mt * 16 + crow + rh * 8) * G_;
#pragma unroll
                    for (int g = 0; g < 3; ++g)
                        gv[mt][rh][g] = *(const float2*)&gp[ro + g * 96 + jc];
                }
        }

        float c[2][3][4];
#pragma unroll
        for (int mt = 0; mt < 2; ++mt)
#pragma unroll
            for (int nt = 0; nt < 3; ++nt)
#pragma unroll
                for (int q = 0; q < 4; ++q) c[mt][nt][q] = 0.f;

        const uint32_t aH = sbase + (uint32_t)(p * 2) * BUFB + lofs;
        const uint32_t aL = aH + BUFB;

#pragma unroll
        for (int kt = 0; kt < 6; ++kt) {
            const uint32_t o = (uint32_t)(kt * 32);
            uint32_t ah0[4], ah1[4], al0[4], al1[4];
            ldsm4(ah0, aH + o);
            ldsm4(ah1, aH + o + 16 * HP2 * 2);
            ldsm4(al0, aL + o);
            ldsm4(al1, aL + o + 16 * HP2 * 2);
            // term 1: Ahi*Bhi
#pragma unroll
            for (int nt = 0; nt < 3; ++nt) {
                mma16816(c[0][nt], ah0, bhi[kt][nt]);
                mma16816(c[1][nt], ah1, bhi[kt][nt]);
            }
            // term 2: Ahi*Blo
#pragma unroll
            for (int nt = 0; nt < 3; ++nt) {
                mma16816(c[0][nt], ah0, blo[kt][nt]);
                mma16816(c[1][nt], ah1, blo[kt][nt]);
            }
            // term 3: Alo*Bhi
#pragma unroll
            for (int nt = 0; nt < 3; ++nt) {
                mma16816(c[0][nt], al0, bhi[kt][nt]);
                mma16816(c[1][nt], al1, bhi[kt][nt]);
            }
        }

        // register elementwise: r,z,n all live in this thread's fragments
        float* op = outp + ((size_t)t * B_ + b0) * H_;
        const int pn = p ^ 1;
#pragma unroll
        for (int mt = 0; mt < 2; ++mt)
#pragma unroll
            for (int rh = 0; rh < 2; ++rh) {
                const int row = mt * 16 + crow + rh * 8;
                float hn2[2];
#pragma unroll
                for (int col = 0; col < 2; ++col) {
                    const int q = rh * 2 + col;
                    const float ir = HAS_GI ? ((col == 0) ? gv[mt][rh][0].x : gv[mt][rh][0].y) : bi[0][col];
                    const float iz = HAS_GI ? ((col == 0) ? gv[mt][rh][1].x : gv[mt][rh][1].y) : bi[1][col];
                    const float in_ = HAS_GI ? ((col == 0) ? gv[mt][rh][2].x : gv[mt][rh][2].y) : bi[2][col];
                    const float rg = sigf(ir + c[mt][0][q] + bh[0][col]);
                    const float zg = sigf(iz + c[mt][1][q] + bh[1][col]);
                    const float ng = tanh_f(in_ + rg * (c[mt][2][q] + bh[2][col]));
                    const float hv = ng + zg * (hold[mt][q] - ng);
                    hold[mt][q] = hv;
                    hn2[col] = hv;
                }
                // write output + split state into next-phase buffers
                *(float2*)&op[(size_t)row * H_ + jc] = make_float2(hn2[0], hn2[1]);
                __nv_bfloat16 hx, lx, hy, ly;
                split2(hn2[0], hx, lx); split2(hn2[1], hy, ly);
                *(uint32_t*)&hb[pn][0][row * HP2 + jc] = pack_bf16(hx, hy);
                *(uint32_t*)&hb[pn][1][row * HP2 + jc] = pack_bf16(lx, ly);
            }
        __syncthreads();
    }
}

// ---------------------------------------------------------------------------
// gi = x @ w_ih^T + b_ih  (tensor-core, persistent blocks; round-2 proven)
// ---------------------------------------------------------------------------
struct BFrags { uint32_t hi[6][4][2]; uint32_t lo[6][4][2]; };

__device__ __forceinline__ void load_bfrags(const float* __restrict__ w, int lane, int ncb, BFrags& bf) {
#pragma unroll
    for (int kt = 0; kt < 6; ++kt)
#pragma unroll
        for (int nt = 0; nt < 4; ++nt) {
            const int g  = ncb + nt * 8 + (lane >> 2);
            const int k0 = kt * 16 + (lane & 3) * 2;
            const float* p = w + (size_t)g * H_ + k0;
            float w0 = p[0], w1 = p[1], w2 = p[8], w3 = p[9];
            __nv_bfloat16 h0, h1, h2, h3, l0, l1, l2, l3;
            split2(w0, h0, l0); split2(w1, h1, l1);
            split2(w2, h2, l2); split2(w3, h3, l3);
            bf.hi[kt][nt][0] = pack_bf16(h0, h1);
            bf.hi[kt][nt][1] = pack_bf16(h2, h3);
            bf.lo[kt][nt][0] = pack_bf16(l0, l1);
            bf.lo[kt][nt][1] = pack_bf16(l2, l3);
        }
}

__global__ void __launch_bounds__(288, 1)
gi_mma(const float* __restrict__ w_ih, const float* __restrict__ b_ih,
       const float* __restrict__ x, float* __restrict__ gi)
{
    __shared__ __align__(16) __nv_bfloat16 xbuf[2 * 32 * HP2];
    __nv_bfloat16* xhi = xbuf;
    __nv_bfloat16* xlo = xbuf + 32 * HP2;

    const int tid  = threadIdx.x;
    const int lane = tid & 31;
    const int wid  = tid >> 5;
    const int ncb  = wid * 32;

    BFrags bf;
    load_bfrags(w_ih, lane, ncb, bf);

    float bv[4][2];
#pragma unroll
    for (int nt = 0; nt < 4; ++nt) {
        const int col = ncb + nt * 8 + 2 * (lane & 3);
        bv[nt][0] = b_ih[col];
        bv[nt][1] = b_ih[col + 1];
    }

    const int j  = tid % 96;
    const int r0 = tid / 96;

    const int arow = (lane & 7) + ((lane >> 3) & 1) * 8;
    const int acol = ((lane >> 4) & 1) * 8;
    const uint32_t aHi = (uint32_t)__cvta_generic_to_shared(xhi) + (uint32_t)((arow * HP2 + acol) * 2);
    const uint32_t aLo = (uint32_t)__cvta_generic_to_shared(xlo) + (uint32_t)((arow * HP2 + acol) * 2);

    const int crow = lane >> 2;
    const int ccol = ncb + 2 * (lane & 3);

    const int ntiles = T_ * B_ / NB_;
    for (int tile = blockIdx.x; tile < ntiles; tile += gridDim.x) {
        const size_t row0 = (size_t)tile * NB_;
#pragma unroll
        for (int i = 0; i < 11; ++i) {
            const int r = r0 + 3 * i;
            if (r < 32) {
                const float v = x[(row0 + r) * H_ + j];
                __nv_bfloat16 h, l; split2(v, h, l);
                xhi[r * HP2 + j] = h; xlo[r * HP2 + j] = l;
            }
        }
        __syncthreads();

        float c[2][4][4];
#pragma unroll
        for (int mt = 0; mt < 2; ++mt)
#pragma unroll
            for (int nt = 0; nt < 4; ++nt)
#pragma unroll
                for (int q = 0; q < 4; ++q) c[mt][nt][q] = 0.f;

#pragma unroll
        for (int kt = 0; kt < 6; ++kt) {
            const uint32_t o = (uint32_t)(kt * 32);
            uint32_t ah0[4], ah1[4], al0[4], al1[4];
            ldsm4(ah0, aHi + o);
            ldsm4(ah1, aHi + o + 16 * HP2 * 2);
            ldsm4(al0, aLo + o);
            ldsm4(al1, aLo + o + 16 * HP2 * 2);
#pragma unroll
            for (int nt = 0; nt < 4; ++nt) {
                mma16816(c[0][nt], ah0, bf.hi[kt][nt]);
                mma16816(c[1][nt], ah1, bf.hi[kt][nt]);
            }
#pragma unroll
            for (int nt = 0; nt < 4; ++nt) {
                mma16816(c[0][nt], ah0, bf.lo[kt][nt]);
                mma16816(c[1][nt], ah1, bf.lo[kt][nt]);
            }
#pragma unroll
            for (int nt = 0; nt < 4; ++nt) {
                mma16816(c[0][nt], al0, bf.hi[kt][nt]);
                mma16816(c[1][nt], al1, bf.hi[kt][nt]);
            }
        }

#pragma unroll
        for (int mt = 0; mt < 2; ++mt)
#pragma unroll
            for (int nt = 0; nt < 4; ++nt) {
                const size_t ra = row0 + mt * 16 + crow;
                const int col   = ccol + nt * 8;
                float2 v01 = make_float2(c[mt][nt][0] + bv[nt][0], c[mt][nt][1] + bv[nt][1]);
                float2 v23 = make_float2(c[mt][nt][2] + bv[nt][0], c[mt][nt][3] + bv[nt][1]);
                *(float2*)(gi + ra * G_ + col)       = v01;
                *(float2*)(gi + (ra + 8) * G_ + col) = v23;
            }
        __syncthreads();
    }
}

// ---------------------------------------------------------------------------
// fc1 (fp32, tiny)
// ---------------------------------------------------------------------------
__global__ void __launch_bounds__(256, 1)
fc1_kernel(const float* __restrict__ z, const float* __restrict__ c,
           const float* __restrict__ w, const float* __restrict__ bias,
           float* __restrict__ h0out)
{
    extern __shared__ float sm[];
    float* wc_s = sm;
    float* xc_s = wc_s + KC * NFCP;

    const int tid = threadIdx.x;
    const int cx  = tid & 31;
    const int ry  = tid >> 5;
    const int b0  = blockIdx.x * NB_;

    float acc[4][12];
#pragma unroll
    for (int m = 0; m < 4; ++m)
#pragma unroll
        for (int i = 0; i < 12; ++i) acc[m][i] = 0.f;

    for (int kc = 0; kc < KIN; kc += KC) {
        for (int idx = tid; idx < NFC * KC; idx += 256) {
            int g = idx / KC, kk = idx - g * KC;
            wc_s[kk * NFCP + g] = w[(size_t)g * KIN + kc + kk];
        }
        for (int idx = tid; idx < NB_ * KC; idx += 256) {
            int r = idx / KC, kk = idx - r * KC;
            int k = kc + kk;
            float v = (k < 256) ? z[(size_t)(b0 + r) * 256 + k]
                                : c[(size_t)(b0 + r) * 256 + (k - 256)];
            xc_s[kk * HPf + r] = v;
        }
        __syncthreads();
#pragma unroll 4
        for (int kk = 0; kk < KC; ++kk) {
            const float a0 = xc_s[kk * HPf + ry +  0];
            const float a1 = xc_s[kk * HPf + ry +  8];
            const float a2 = xc_s[kk * HPf + ry + 16];
            const float a3 = xc_s[kk * HPf + ry + 24];
            const float* wr = wc_s + kk * NFCP + cx;
#pragma unroll
            for (int i = 0; i < 12; ++i) {
                const float wv = wr[32 * i];
                acc[0][i] = fmaf(a0, wv, acc[0][i]);
                acc[1][i] = fmaf(a1, wv, acc[1][i]);
                acc[2][i] = fmaf(a2, wv, acc[2][i]);
                acc[3][i] = fmaf(a3, wv, acc[3][i]);
            }
        }
        __syncthreads();
    }

#pragma unroll
    for (int m = 0; m < 4; ++m) {
        const int r = b0 + ry + 8 * m;
#pragma unroll
        for (int i = 0; i < 12; ++i) {
            const int g = cx + 32 * i;
            float v = acc[m][i] + bias[g];
            v = (v >= 0.f) ? v : 0.2f * v;
            h0out[(size_t)r * NFC + g] = v;
        }
    }
}

// ---------------------------------------------------------------------------
// [T,B,H] -> [B,H,T] transpose
// ---------------------------------------------------------------------------
__global__ void transpose_kernel(const float* __restrict__ in, float* __restrict__ outp)
{
    __shared__ float tile[32][33];
    const int b  = blockIdx.z;
    const int j0 = blockIdx.y * 32;
    const int t0 = blockIdx.x * 32;
    const int tx = threadIdx.x, ty = threadIdx.y;

#pragma unroll
    for (int yy = ty; yy < 32; yy += 8) {
        const int t = t0 + yy;
        if (t < T_) tile[yy][tx] = in[((size_t)t * B_ + b) * H_ + j0 + tx];
    }
    __syncthreads();
#pragma unroll
    for (int yy = ty; yy < 32; yy += 8) {
        const int t = t0 + tx;
        const int j = j0 + yy;
        if (t < T_) outp[((size_t)b * H_ + j) * T_ + t] = tile[tx][yy];
    }
}

// ---------------------------------------------------------------------------
extern "C" void kernel_launch(void* const* d_in, const int* in_sizes, int n_in,
                              void* d_out, int out_size)
{
    const float* z     = (const float*)d_in[0];
    const float* c     = (const float*)d_in[1];
    const float* fc1_w = (const float*)d_in[2];
    const float* fc1_b = (const float*)d_in[3];
    const float* w_ih  = (const float*)d_in[4];
    const float* w_hh  = (const float*)d_in[5];
    const float* b_ih  = (const float*)d_in[6];
    const float* b_hh  = (const float*)d_in[7];
    float* out = (float*)d_out;

    float *bufA, *bufB, *giBuf, *h0Buf;
    cudaGetSymbolAddress((void**)&bufA,  g_bufA);
    cudaGetSymbolAddress((void**)&bufB,  g_bufB);
    cudaGetSymbolAddress((void**)&giBuf, g_gi);
    cudaGetSymbolAddress((void**)&h0Buf, g_h0);

    const size_t fcSm = (size_t)(KC * NFCP + KC * HPf) * sizeof(float);
    cudaFuncSetAttribute(fc1_kernel, cudaFuncAttributeMaxDynamicSharedMemorySize, (int)fcSm);

    const int nblk = B_ / NB_;  // 128

    fc1_kernel<<<nblk, 256, fcSm>>>(z, c, fc1_w, fc1_b, h0Buf);

    // layer 0 (input zeros: gi == b_ih)
    scan2<false><<<nblk, 384>>>(w_hh, b_hh, b_ih, h0Buf, nullptr, bufA);

    // layers 1..3
    const float* srcs[3] = {bufA, bufB, bufA};
    float*       dsts[3] = {bufB, bufA, bufB};
    for (int l = 1; l < 4; ++l) {
        const size_t wo = (size_t)l * G_ * H_;
        const size_t bo = (size_t)l * G_;
        gi_mma<<<148, 288>>>(w_ih + wo, b_ih + bo, srcs[l - 1], giBuf);
        scan2<true><<<nblk, 384>>>(w_hh + wo, b_hh + bo, b_ih + bo,
                                   h0Buf + (size_t)l * B_ * H_, giBuf, dsts[l - 1]);
    }

    transpose_kernel<<<dim3(8, 3, B_), dim3(32, 8)>>>(bufB, out);
}

// round 7
// speedup vs baseline: 1.6181x; 1.2099x over previous
#include <cuda_runtime.h>
#include <cuda_bf16.h>
#include <cstdint>
#include <cstddef>

// ---------------------------------------------------------------------------
constexpr int H_  = 96;
constexpr int G_  = 288;
constexpr int T_  = 239;
constexpr int B_  = 4096;
constexpr int NB_ = 32;

constexpr int HP2 = 104;   // bf16 pitch for A (h/x) ldmatrix tiles
constexpr int PW  = 104;   // bf16 pitch for w_ih smem rows (conflict-free)

constexpr int KIN  = 512;
constexpr int NFC  = 384;
constexpr int NFCP = 385;
constexpr int KC   = 64;
constexpr int HPf  = 33;

constexpr size_t SZ_SEQ = (size_t)T_ * B_ * H_;
constexpr size_t SZ_H0  = (size_t)B_ * NFC;

__device__ float g_bufA[SZ_SEQ];
__device__ float g_bufB[SZ_SEQ];
__device__ float g_h0  [SZ_H0];

// ---------------------------------------------------------------------------
__device__ __forceinline__ float sigf(float x)   { return 1.0f / (1.0f + __expf(-x)); }
__device__ __forceinline__ float tanh_f(float x) { return 2.0f / (1.0f + __expf(-2.0f * x)) - 1.0f; }

__device__ __forceinline__ uint32_t pack_bf16(__nv_bfloat16 a, __nv_bfloat16 b) {
    return (uint32_t)__bfloat16_as_ushort(a) | ((uint32_t)__bfloat16_as_ushort(b) << 16);
}
__device__ __forceinline__ void split2(float x, __nv_bfloat16& h, __nv_bfloat16& l) {
    h = __float2bfloat16(x);
    l = __float2bfloat16(x - __bfloat162float(h));
}

__device__ __forceinline__ void mma16816(float c[4], const uint32_t a[4], const uint32_t b[2]) {
    asm volatile(
        "mma.sync.aligned.m16n8k16.row.col.f32.bf16.bf16.f32 "
        "{%0,%1,%2,%3}, {%4,%5,%6,%7}, {%8,%9}, {%0,%1,%2,%3};"
        : "+f"(c[0]), "+f"(c[1]), "+f"(c[2]), "+f"(c[3])
        : "r"(a[0]), "r"(a[1]), "r"(a[2]), "r"(a[3]), "r"(b[0]), "r"(b[1]));
}
__device__ __forceinline__ void ldsm4(uint32_t r[4], uint32_t addr) {
    asm volatile("ldmatrix.sync.aligned.m8n8.x4.shared.b16 {%0,%1,%2,%3}, [%4];"
                 : "=r"(r[0]), "=r"(r[1]), "=r"(r[2]), "=r"(r[3]) : "r"(addr));
}

// ---------------------------------------------------------------------------
// Fused GRU scan: gh AND gi GEMMs per step on tensor cores.
// 384 threads = 12 warps; warp w owns j in [8w, 8w+8), gate cols at +0,+96,+192.
// w_hh split-bf16 fragments in registers; w_ih split-bf16 in smem.
// n-gate input term accumulated SEPARATELY (cx) — must stay outside r*(...).
// ---------------------------------------------------------------------------
template <bool FUSED>
__global__ void __launch_bounds__(384, 1)
scanF(const float* __restrict__ w_hh, const float* __restrict__ b_hh,
      const float* __restrict__ w_ih, const float* __restrict__ b_ih,
      const float* __restrict__ h0,   const float* __restrict__ x,
      float* __restrict__ outp)
{
    extern __shared__ __align__(16) char smraw[];
    __nv_bfloat16* wHi = (__nv_bfloat16*)smraw;
    __nv_bfloat16* wLo = wHi + (FUSED ? G_ * PW : 0);
    __nv_bfloat16* hb  = wLo + (FUSED ? G_ * PW : 0);
    __nv_bfloat16* xb  = hb + 4 * 32 * HP2;
    float* bias_s      = (float*)(xb + (FUSED ? 4 * 32 * HP2 : 0));

    const int tid  = threadIdx.x;
    const int lane = tid & 31;
    const int w    = tid >> 5;          // 0..11
    const int b0   = blockIdx.x * NB_;

    // --- w_hh fragments in registers (r,z,n tiles for this warp's 8 j-cols) ---
    uint32_t bhi[6][3][2], blo[6][3][2];
#pragma unroll
    for (int kt = 0; kt < 6; ++kt)
#pragma unroll
        for (int nt = 0; nt < 3; ++nt) {
            const int g  = nt * 96 + 8 * w + (lane >> 2);
            const int k0 = kt * 16 + (lane & 3) * 2;
            const float* p = w_hh + (size_t)g * H_ + k0;
            float w0 = p[0], w1 = p[1], w2 = p[8], w3 = p[9];
            __nv_bfloat16 h0b, h1b, h2b, h3b, l0b, l1b, l2b, l3b;
            split2(w0, h0b, l0b); split2(w1, h1b, l1b);
            split2(w2, h2b, l2b); split2(w3, h3b, l3b);
            bhi[kt][nt][0] = pack_bf16(h0b, h1b);
            bhi[kt][nt][1] = pack_bf16(h2b, h3b);
            blo[kt][nt][0] = pack_bf16(l0b, l1b);
            blo[kt][nt][1] = pack_bf16(l2b, l3b);
        }

    // --- w_ih split into smem (FUSED only) ---
    if (FUSED) {
        for (int i = tid; i < G_ * H_; i += 384) {
            const int g = i / H_, k = i - g * H_;
            __nv_bfloat16 h, l; split2(w_ih[i], h, l);
            wHi[g * PW + k] = h;
            wLo[g * PW + k] = l;
        }
    }
    if (tid < G_) {
        bias_s[tid]      = b_hh[tid];
        bias_s[G_ + tid] = b_ih[tid];
    }

    const int crow = lane >> 2;
    const int jc   = 8 * w + 2 * (lane & 3);

    // --- init h state: registers + bf16 split buffers (phase 0) ---
    float hold[2][4];
#pragma unroll
    for (int mt = 0; mt < 2; ++mt)
#pragma unroll
        for (int rh = 0; rh < 2; ++rh) {
            const int row = mt * 16 + crow + rh * 8;
            const float2 v = *(const float2*)&h0[(size_t)(b0 + row) * H_ + jc];
            hold[mt][rh * 2]     = v.x;
            hold[mt][rh * 2 + 1] = v.y;
            __nv_bfloat16 hx, lx, hy, ly;
            split2(v.x, hx, lx); split2(v.y, hy, ly);
            *(uint32_t*)&hb[(0 * 2 + 0) * 32 * HP2 + row * HP2 + jc] = pack_bf16(hx, hy);
            *(uint32_t*)&hb[(0 * 2 + 1) * 32 * HP2 + row * HP2 + jc] = pack_bf16(lx, ly);
        }

    // --- prologue: x(0) into xb phase 0 ---
    float2 xr[2][2];
    if (FUSED) {
#pragma unroll
        for (int mt = 0; mt < 2; ++mt)
#pragma unroll
            for (int rh = 0; rh < 2; ++rh) {
                const int row = mt * 16 + crow + rh * 8;
                xr[mt][rh] = *(const float2*)&x[(size_t)(b0 + row) * H_ + jc];
                __nv_bfloat16 hx, lx, hy, ly;
                split2(xr[mt][rh].x, hx, lx); split2(xr[mt][rh].y, hy, ly);
                *(uint32_t*)&xb[(0 * 2 + 0) * 32 * HP2 + row * HP2 + jc] = pack_bf16(hx, hy);
                *(uint32_t*)&xb[(0 * 2 + 1) * 32 * HP2 + row * HP2 + jc] = pack_bf16(lx, ly);
            }
    }
    __syncthreads();

    // ldmatrix per-lane offsets
    const int arow = (lane & 7) + ((lane >> 3) & 1) * 8;
    const int acol = ((lane >> 4) & 1) * 8;
    const uint32_t lofs = (uint32_t)((arow * HP2 + acol) * 2);
    const uint32_t hBase = (uint32_t)__cvta_generic_to_shared(hb) + lofs;
    const uint32_t xBase = (uint32_t)__cvta_generic_to_shared(xb) + lofs;
    constexpr uint32_t BUFB = (uint32_t)(32 * HP2 * 2);

    const int wcol0 = 8 * w + (lane >> 2);
    const int wk0   = (lane & 3) * 2;

    for (int t = 0; t < T_; ++t) {
        const int p  = t & 1;
        const int pn = p ^ 1;

        // prefetch x(t+1)
        if (FUSED) {
            const int tn = (t + 1 < T_) ? (t + 1) : (T_ - 1);
            const float* xp = x + ((size_t)tn * B_ + b0) * H_;
#pragma unroll
            for (int mt = 0; mt < 2; ++mt)
#pragma unroll
                for (int rh = 0; rh < 2; ++rh) {
                    const int row = mt * 16 + crow + rh * 8;
                    xr[mt][rh] = *(const float2*)&xp[(size_t)row * H_ + jc];
                }
        }

        float c[2][3][4];   // r, z, n(hidden part)
        float cx[2][4];     // n(input part) — kept separate!
#pragma unroll
        for (int mt = 0; mt < 2; ++mt) {
#pragma unroll
            for (int nt = 0; nt < 3; ++nt)
#pragma unroll
                for (int q = 0; q < 4; ++q) c[mt][nt][q] = 0.f;
#pragma unroll
            for (int q = 0; q < 4; ++q) cx[mt][q] = 0.f;
        }

        const uint32_t aHh = hBase + (uint32_t)(p * 2) * BUFB;
        const uint32_t aLh = aHh + BUFB;
        const uint32_t aHx = xBase + (uint32_t)(p * 2) * BUFB;
        const uint32_t aLx = aHx + BUFB;

#pragma unroll
        for (int kt = 0; kt < 6; ++kt) {
            const uint32_t o = (uint32_t)(kt * 32);
            uint32_t ah0[4], ah1[4], al0[4], al1[4];
            ldsm4(ah0, aHh + o);
            ldsm4(ah1, aHh + o + 16 * HP2 * 2);
            ldsm4(al0, aLh + o);
            ldsm4(al1, aLh + o + 16 * HP2 * 2);
            // h GEMM: hi*hi, hi*lo, lo*hi
#pragma unroll
            for (int nt = 0; nt < 3; ++nt) {
                mma16816(c[0][nt], ah0, bhi[kt][nt]);
                mma16816(c[1][nt], ah1, bhi[kt][nt]);
            }
#pragma unroll
            for (int nt = 0; nt < 3; ++nt) {
                mma16816(c[0][nt], ah0, blo[kt][nt]);
                mma16816(c[1][nt], ah1, blo[kt][nt]);
            }
#pragma unroll
            for (int nt = 0; nt < 3; ++nt) {
                mma16816(c[0][nt], al0, bhi[kt][nt]);
                mma16816(c[1][nt], al1, bhi[kt][nt]);
            }
            if (FUSED) {
                uint32_t xh0[4], xh1[4], xl0[4], xl1[4];
                ldsm4(xh0, aHx + o);
                ldsm4(xh1, aHx + o + 16 * HP2 * 2);
                ldsm4(xl0, aLx + o);
                ldsm4(xl1, aLx + o + 16 * HP2 * 2);
                uint32_t bxh[3][2], bxl[3][2];
#pragma unroll
                for (int nt = 0; nt < 3; ++nt) {
                    const int cidx = (nt * 96 + wcol0) * PW + kt * 16 + wk0;
                    bxh[nt][0] = *(const uint32_t*)&wHi[cidx];
                    bxh[nt][1] = *(const uint32_t*)&wHi[cidx + 8];
                    bxl[nt][0] = *(const uint32_t*)&wLo[cidx];
                    bxl[nt][1] = *(const uint32_t*)&wLo[cidx + 8];
                }
                // x GEMM: r,z gates -> c[ ][0..1]; n gate -> cx (separate!)
                mma16816(c[0][0], xh0, bxh[0]);
                mma16816(c[1][0], xh1, bxh[0]);
                mma16816(c[0][1], xh0, bxh[1]);
                mma16816(c[1][1], xh1, bxh[1]);
                mma16816(cx[0],   xh0, bxh[2]);
                mma16816(cx[1],   xh1, bxh[2]);

                mma16816(c[0][0], xh0, bxl[0]);
                mma16816(c[1][0], xh1, bxl[0]);
                mma16816(c[0][1], xh0, bxl[1]);
                mma16816(c[1][1], xh1, bxl[1]);
                mma16816(cx[0],   xh0, bxl[2]);
                mma16816(cx[1],   xh1, bxl[2]);

                mma16816(c[0][0], xl0, bxh[0]);
                mma16816(c[1][0], xl1, bxh[0]);
                mma16816(c[0][1], xl0, bxh[1]);
                mma16816(c[1][1], xl1, bxh[1]);
                mma16816(cx[0],   xl0, bxh[2]);
                mma16816(cx[1],   xl1, bxh[2]);
            }
        }

        float2 bhv[3], biv[3];
#pragma unroll
        for (int g = 0; g < 3; ++g) {
            bhv[g] = *(const float2*)&bias_s[g * 96 + jc];
            biv[g] = *(const float2*)&bias_s[G_ + g * 96 + jc];
        }

        float* op = outp + ((size_t)t * B_ + b0) * H_;
#pragma unroll
        for (int mt = 0; mt < 2; ++mt)
#pragma unroll
            for (int rh = 0; rh < 2; ++rh) {
                const int row = mt * 16 + crow + rh * 8;
                float hn2[2];
#pragma unroll
                for (int col = 0; col < 2; ++col) {
                    const int q = rh * 2 + col;
                    const float bhr = (col == 0) ? bhv[0].x : bhv[0].y;
                    const float bhz = (col == 0) ? bhv[1].x : bhv[1].y;
                    const float bhn = (col == 0) ? bhv[2].x : bhv[2].y;
                    const float bir = (col == 0) ? biv[0].x : biv[0].y;
                    const float biz = (col == 0) ? biv[1].x : biv[1].y;
                    const float bin = (col == 0) ? biv[2].x : biv[2].y;
                    const float rg = sigf(bir + c[mt][0][q] + bhr);
                    const float zg = sigf(biz + c[mt][1][q] + bhz);
                    // n-gate: input term (cx) OUTSIDE r; hidden term inside.
                    const float ng = tanh_f(bin + cx[mt][q] + rg * (c[mt][2][q] + bhn));
                    const float hv = ng + zg * (hold[mt][q] - ng);
                    hold[mt][q] = hv;
                    hn2[col] = hv;
                }
                *(float2*)&op[(size_t)row * H_ + jc] = make_float2(hn2[0], hn2[1]);
                __nv_bfloat16 hx, lx, hy, ly;
                split2(hn2[0], hx, lx); split2(hn2[1], hy, ly);
                *(uint32_t*)&hb[(pn * 2 + 0) * 32 * HP2 + row * HP2 + jc] = pack_bf16(hx, hy);
                *(uint32_t*)&hb[(pn * 2 + 1) * 32 * HP2 + row * HP2 + jc] = pack_bf16(lx, ly);
            }

        if (FUSED) {
#pragma unroll
            for (int mt = 0; mt < 2; ++mt)
#pragma unroll
                for (int rh = 0; rh < 2; ++rh) {
                    const int row = mt * 16 + crow + rh * 8;
                    __nv_bfloat16 hx, lx, hy, ly;
                    split2(xr[mt][rh].x, hx, lx); split2(xr[mt][rh].y, hy, ly);
                    *(uint32_t*)&xb[(pn * 2 + 0) * 32 * HP2 + row * HP2 + jc] = pack_bf16(hx, hy);
                    *(uint32_t*)&xb[(pn * 2 + 1) * 32 * HP2 + row * HP2 + jc] = pack_bf16(lx, ly);
                }
        }
        __syncthreads();
    }
}

// ---------------------------------------------------------------------------
// fc1 (fp32, tiny)
// ---------------------------------------------------------------------------
__global__ void __launch_bounds__(256, 1)
fc1_kernel(const float* __restrict__ z, const float* __restrict__ c,
           const float* __restrict__ w, const float* __restrict__ bias,
           float* __restrict__ h0out)
{
    extern __shared__ float sm[];
    float* wc_s = sm;
    float* xc_s = wc_s + KC * NFCP;

    const int tid = threadIdx.x;
    const int cx  = tid & 31;
    const int ry  = tid >> 5;
    const int b0  = blockIdx.x * NB_;

    float acc[4][12];
#pragma unroll
    for (int m = 0; m < 4; ++m)
#pragma unroll
        for (int i = 0; i < 12; ++i) acc[m][i] = 0.f;

    for (int kc = 0; kc < KIN; kc += KC) {
        for (int idx = tid; idx < NFC * KC; idx += 256) {
            int g = idx / KC, kk = idx - g * KC;
            wc_s[kk * NFCP + g] = w[(size_t)g * KIN + kc + kk];
        }
        for (int idx = tid; idx < NB_ * KC; idx += 256) {
            int r = idx / KC, kk = idx - r * KC;
            int k = kc + kk;
            float v = (k < 256) ? z[(size_t)(b0 + r) * 256 + k]
                                : c[(size_t)(b0 + r) * 256 + (k - 256)];
            xc_s[kk * HPf + r] = v;
        }
        __syncthreads();
#pragma unroll 4
        for (int kk = 0; kk < KC; ++kk) {
            const float a0 = xc_s[kk * HPf + ry +  0];
            const float a1 = xc_s[kk * HPf + ry +  8];
            const float a2 = xc_s[kk * HPf + ry + 16];
            const float a3 = xc_s[kk * HPf + ry + 24];
            const float* wr = wc_s + kk * NFCP + cx;
#pragma unroll
            for (int i = 0; i < 12; ++i) {
                const float wv = wr[32 * i];
                acc[0][i] = fmaf(a0, wv, acc[0][i]);
                acc[1][i] = fmaf(a1, wv, acc[1][i]);
                acc[2][i] = fmaf(a2, wv, acc[2][i]);
                acc[3][i] = fmaf(a3, wv, acc[3][i]);
            }
        }
        __syncthreads();
    }

#pragma unroll
    for (int m = 0; m < 4; ++m) {
        const int r = b0 + ry + 8 * m;
#pragma unroll
        for (int i = 0; i < 12; ++i) {
            const int g = cx + 32 * i;
            float v = acc[m][i] + bias[g];
            v = (v >= 0.f) ? v : 0.2f * v;
            h0out[(size_t)r * NFC + g] = v;
        }
    }
}

// ---------------------------------------------------------------------------
// [T,B,H] -> [B,H,T] transpose
// ---------------------------------------------------------------------------
__global__ void transpose_kernel(const float* __restrict__ in, float* __restrict__ outp)
{
    __shared__ float tile[32][33];
    const int b  = blockIdx.z;
    const int j0 = blockIdx.y * 32;
    const int t0 = blockIdx.x * 32;
    const int tx = threadIdx.x, ty = threadIdx.y;

#pragma unroll
    for (int yy = ty; yy < 32; yy += 8) {
        const int t = t0 + yy;
        if (t < T_) tile[yy][tx] = in[((size_t)t * B_ + b) * H_ + j0 + tx];
    }
    __syncthreads();
#pragma unroll
    for (int yy = ty; yy < 32; yy += 8) {
        const int t = t0 + tx;
        const int j = j0 + yy;
        if (t < T_) outp[((size_t)b * H_ + j) * T_ + t] = tile[tx][yy];
    }
}

// ---------------------------------------------------------------------------
extern "C" void kernel_launch(void* const* d_in, const int* in_sizes, int n_in,
                              void* d_out, int out_size)
{
    const float* z     = (const float*)d_in[0];
    const float* c     = (const float*)d_in[1];
    const float* fc1_w = (const float*)d_in[2];
    const float* fc1_b = (const float*)d_in[3];
    const float* w_ih  = (const float*)d_in[4];
    const float* w_hh  = (const float*)d_in[5];
    const float* b_ih  = (const float*)d_in[6];
    const float* b_hh  = (const float*)d_in[7];
    float* out = (float*)d_out;

    float *bufA, *bufB, *h0Buf;
    cudaGetSymbolAddress((void**)&bufA,  g_bufA);
    cudaGetSymbolAddress((void**)&bufB,  g_bufB);
    cudaGetSymbolAddress((void**)&h0Buf, g_h0);

    const size_t smF = (size_t)(2 * G_ * PW + 8 * 32 * HP2) * sizeof(__nv_bfloat16)
                     + (size_t)(2 * G_) * sizeof(float);        // 175,360 B
    const size_t sm0 = (size_t)(4 * 32 * HP2) * sizeof(__nv_bfloat16)
                     + (size_t)(2 * G_) * sizeof(float);        // 28,928 B
    const size_t fcSm = (size_t)(KC * NFCP + KC * HPf) * sizeof(float);

    cudaFuncSetAttribute(scanF<false>, cudaFuncAttributeMaxDynamicSharedMemorySize, (int)sm0);
    cudaFuncSetAttribute(scanF<true>,  cudaFuncAttributeMaxDynamicSharedMemorySize, (int)smF);
    cudaFuncSetAttribute(fc1_kernel,   cudaFuncAttributeMaxDynamicSharedMemorySize, (int)fcSm);

    const int nblk = B_ / NB_;  // 128

    fc1_kernel<<<nblk, 256, fcSm>>>(z, c, fc1_w, fc1_b, h0Buf);

    // layer 0: input zeros (gi_n == 0, biases handled in elementwise)
    scanF<false><<<nblk, 384, sm0>>>(w_hh, b_hh, nullptr, b_ih, h0Buf, nullptr, bufA);

    // layers 1..3: fused gi + scan
    const float* srcs[3] = {bufA, bufB, bufA};
    float*       dsts[3] = {bufB, bufA, bufB};
    for (int l = 1; l < 4; ++l) {
        const size_t wo = (size_t)l * G_ * H_;
        const size_t bo = (size_t)l * G_;
        scanF<true><<<nblk, 384, smF>>>(w_hh + wo, b_hh + bo, w_ih + wo, b_ih + bo,
                                        h0Buf + (size_t)l * B_ * H_, srcs[l - 1], dsts[l - 1]);
    }

    transpose_kernel<<<dim3(8, 3, B_), dim3(32, 8)>>>(bufB, out);
}

// round 8
// speedup vs baseline: 1.9940x; 1.2323x over previous
#include <cuda_runtime.h>
#include <cuda_fp16.h>
#include <cstdint>
#include <cstddef>

// ---------------------------------------------------------------------------
constexpr int H_  = 96;
constexpr int G_  = 288;
constexpr int T_  = 239;
constexpr int B_  = 4096;
constexpr int NB_ = 32;

constexpr int HP2 = 104;   // fp16 pitch for A (h/x) ldmatrix tiles
constexpr int PW  = 104;   // fp16 pitch for w_ih smem rows

constexpr int KIN  = 512;
constexpr int NFC  = 384;
constexpr int NFCP = 385;
constexpr int KC   = 64;
constexpr int HPf  = 33;

constexpr size_t SZ_SEQ = (size_t)T_ * B_ * H_;
constexpr size_t SZ_H0  = (size_t)B_ * NFC;

__device__ float g_bufA[SZ_SEQ];
__device__ float g_bufB[SZ_SEQ];
__device__ float g_h0  [SZ_H0];

// ---------------------------------------------------------------------------
__device__ __forceinline__ float sigf(float x)   { return 1.0f / (1.0f + __expf(-x)); }
__device__ __forceinline__ float tanh_f(float x) { return 2.0f / (1.0f + __expf(-2.0f * x)) - 1.0f; }

__device__ __forceinline__ uint32_t pack_h2(__half a, __half b) {
    return (uint32_t)__half_as_ushort(a) | ((uint32_t)__half_as_ushort(b) << 16);
}
__device__ __forceinline__ void split2h(float x, __half& h, __half& l) {
    h = __float2half_rn(x);
    l = __float2half_rn(x - __half2float(h));
}

__device__ __forceinline__ void mma16816(float c[4], const uint32_t a[4], const uint32_t b[2]) {
    asm volatile(
        "mma.sync.aligned.m16n8k16.row.col.f32.f16.f16.f32 "
        "{%0,%1,%2,%3}, {%4,%5,%6,%7}, {%8,%9}, {%0,%1,%2,%3};"
        : "+f"(c[0]), "+f"(c[1]), "+f"(c[2]), "+f"(c[3])
        : "r"(a[0]), "r"(a[1]), "r"(a[2]), "r"(a[3]), "r"(b[0]), "r"(b[1]));
}
__device__ __forceinline__ void ldsm4(uint32_t r[4], uint32_t addr) {
    asm volatile("ldmatrix.sync.aligned.m8n8.x4.shared.b16 {%0,%1,%2,%3}, [%4];"
                 : "=r"(r[0]), "=r"(r[1]), "=r"(r[2]), "=r"(r[3]) : "r"(addr));
}

// ---------------------------------------------------------------------------
// Fused GRU scan, fp16 scheme: A (h/x) single fp16; weights 2-term fp16 split.
// 384 threads = 12 warps; warp w owns j in [8w, 8w+8), gate cols at +0,+96,+192.
// w_hh split fragments in registers; w_ih split in smem.
// n-gate input term accumulated SEPARATELY (cx) — stays outside r*( ).
// ---------------------------------------------------------------------------
template <bool FUSED>
__global__ void __launch_bounds__(384, 1)
scanF(const float* __restrict__ w_hh, const float* __restrict__ b_hh,
      const float* __restrict__ w_ih, const float* __restrict__ b_ih,
      const float* __restrict__ h0,   const float* __restrict__ x,
      float* __restrict__ outp)
{
    extern __shared__ __align__(16) char smraw[];
    __half* wHi = (__half*)smraw;
    __half* wLo = wHi + (FUSED ? G_ * PW : 0);
    __half* hb  = wLo + (FUSED ? G_ * PW : 0);      // [2 phases][32*HP2]
    __half* xb  = hb + 2 * 32 * HP2;                // [2 phases][32*HP2] (FUSED)
    float* bias_s = (float*)(xb + (FUSED ? 2 * 32 * HP2 : 0));

    const int tid  = threadIdx.x;
    const int lane = tid & 31;
    const int w    = tid >> 5;          // 0..11
    const int b0   = blockIdx.x * NB_;

    // --- w_hh 2-term fp16 fragments in registers ---
    uint32_t bhi[6][3][2], blo[6][3][2];
#pragma unroll
    for (int kt = 0; kt < 6; ++kt)
#pragma unroll
        for (int nt = 0; nt < 3; ++nt) {
            const int g  = nt * 96 + 8 * w + (lane >> 2);
            const int k0 = kt * 16 + (lane & 3) * 2;
            const float* p = w_hh + (size_t)g * H_ + k0;
            float w0 = p[0], w1 = p[1], w2 = p[8], w3 = p[9];
            __half h0b, h1b, h2b, h3b, l0b, l1b, l2b, l3b;
            split2h(w0, h0b, l0b); split2h(w1, h1b, l1b);
            split2h(w2, h2b, l2b); split2h(w3, h3b, l3b);
            bhi[kt][nt][0] = pack_h2(h0b, h1b);
            bhi[kt][nt][1] = pack_h2(h2b, h3b);
            blo[kt][nt][0] = pack_h2(l0b, l1b);
            blo[kt][nt][1] = pack_h2(l2b, l3b);
        }

    // --- w_ih 2-term split into smem (FUSED only) ---
    if (FUSED) {
        for (int i = tid; i < G_ * H_; i += 384) {
            const int g = i / H_, k = i - g * H_;
            __half h, l; split2h(w_ih[i], h, l);
            wHi[g * PW + k] = h;
            wLo[g * PW + k] = l;
        }
    }
    if (tid < G_) {
        bias_s[tid]      = b_hh[tid];
        bias_s[G_ + tid] = b_ih[tid];
    }

    const int crow = lane >> 2;
    const int jc   = 8 * w + 2 * (lane & 3);

    // --- init h state: registers + single fp16 buffer (phase 0) ---
    float hold[2][4];
#pragma unroll
    for (int mt = 0; mt < 2; ++mt)
#pragma unroll
        for (int rh = 0; rh < 2; ++rh) {
            const int row = mt * 16 + crow + rh * 8;
            const float2 v = *(const float2*)&h0[(size_t)(b0 + row) * H_ + jc];
            hold[mt][rh * 2]     = v.x;
            hold[mt][rh * 2 + 1] = v.y;
            *(uint32_t*)&hb[0 * 32 * HP2 + row * HP2 + jc] =
                pack_h2(__float2half_rn(v.x), __float2half_rn(v.y));
        }

    // --- prologue: x(0) into xb phase 0 ---
    float2 xr[2][2];
    if (FUSED) {
#pragma unroll
        for (int mt = 0; mt < 2; ++mt)
#pragma unroll
            for (int rh = 0; rh < 2; ++rh) {
                const int row = mt * 16 + crow + rh * 8;
                xr[mt][rh] = *(const float2*)&x[(size_t)(b0 + row) * H_ + jc];
                *(uint32_t*)&xb[0 * 32 * HP2 + row * HP2 + jc] =
                    pack_h2(__float2half_rn(xr[mt][rh].x), __float2half_rn(xr[mt][rh].y));
            }
    }
    __syncthreads();

    // ldmatrix per-lane offsets
    const int arow = (lane & 7) + ((lane >> 3) & 1) * 8;
    const int acol = ((lane >> 4) & 1) * 8;
    const uint32_t lofs = (uint32_t)((arow * HP2 + acol) * 2);
    const uint32_t hBase = (uint32_t)__cvta_generic_to_shared(hb) + lofs;
    const uint32_t xBase = (uint32_t)__cvta_generic_to_shared(xb) + lofs;
    constexpr uint32_t BUFB = (uint32_t)(32 * HP2 * 2);   // bytes per phase buffer

    const int wcol0 = 8 * w + (lane >> 2);
    const int wk0   = (lane & 3) * 2;

    for (int t = 0; t < T_; ++t) {
        const int p  = t & 1;
        const int pn = p ^ 1;

        // prefetch x(t+1)
        if (FUSED) {
            const int tn = (t + 1 < T_) ? (t + 1) : (T_ - 1);
            const float* xp = x + ((size_t)tn * B_ + b0) * H_;
#pragma unroll
            for (int mt = 0; mt < 2; ++mt)
#pragma unroll
                for (int rh = 0; rh < 2; ++rh) {
                    const int row = mt * 16 + crow + rh * 8;
                    xr[mt][rh] = *(const float2*)&xp[(size_t)row * H_ + jc];
                }
        }

        float c[2][3][4];   // r, z, n(hidden)
        float cx[2][4];     // n(input) — separate
#pragma unroll
        for (int mt = 0; mt < 2; ++mt) {
#pragma unroll
            for (int nt = 0; nt < 3; ++nt)
#pragma unroll
                for (int q = 0; q < 4; ++q) c[mt][nt][q] = 0.f;
#pragma unroll
            for (int q = 0; q < 4; ++q) cx[mt][q] = 0.f;
        }

        const uint32_t aH = hBase + (uint32_t)p * BUFB;
        const uint32_t aX = xBase + (uint32_t)p * BUFB;

#pragma unroll
        for (int kt = 0; kt < 6; ++kt) {
            const uint32_t o = (uint32_t)(kt * 32);
            uint32_t ah0[4], ah1[4];
            ldsm4(ah0, aH + o);
            ldsm4(ah1, aH + o + 16 * HP2 * 2);
            // h GEMM: a * (whi + wlo)
#pragma unroll
            for (int nt = 0; nt < 3; ++nt) {
                mma16816(c[0][nt], ah0, bhi[kt][nt]);
                mma16816(c[1][nt], ah1, bhi[kt][nt]);
            }
#pragma unroll
            for (int nt = 0; nt < 3; ++nt) {
                mma16816(c[0][nt], ah0, blo[kt][nt]);
                mma16816(c[1][nt], ah1, blo[kt][nt]);
            }
            if (FUSED) {
                uint32_t xh0[4], xh1[4];
                ldsm4(xh0, aX + o);
                ldsm4(xh1, aX + o + 16 * HP2 * 2);
                uint32_t bxh[3][2], bxl[3][2];
#pragma unroll
                for (int nt = 0; nt < 3; ++nt) {
                    const int cidx = (nt * 96 + wcol0) * PW + kt * 16 + wk0;
                    bxh[nt][0] = *(const uint32_t*)&wHi[cidx];
                    bxh[nt][1] = *(const uint32_t*)&wHi[cidx + 8];
                    bxl[nt][0] = *(const uint32_t*)&wLo[cidx];
                    bxl[nt][1] = *(const uint32_t*)&wLo[cidx + 8];
                }
                // x GEMM: r,z -> c[][0..1]; n -> cx (separate!)
                mma16816(c[0][0], xh0, bxh[0]);
                mma16816(c[1][0], xh1, bxh[0]);
                mma16816(c[0][1], xh0, bxh[1]);
                mma16816(c[1][1], xh1, bxh[1]);
                mma16816(cx[0],   xh0, bxh[2]);
                mma16816(cx[1],   xh1, bxh[2]);

                mma16816(c[0][0], xh0, bxl[0]);
                mma16816(c[1][0], xh1, bxl[0]);
                mma16816(c[0][1], xh0, bxl[1]);
                mma16816(c[1][1], xh1, bxl[1]);
                mma16816(cx[0],   xh0, bxl[2]);
                mma16816(cx[1],   xh1, bxl[2]);
            }
        }

        float2 bhv[3], biv[3];
#pragma unroll
        for (int g = 0; g < 3; ++g) {
            bhv[g] = *(const float2*)&bias_s[g * 96 + jc];
            biv[g] = *(const float2*)&bias_s[G_ + g * 96 + jc];
        }

        float* op = outp + ((size_t)t * B_ + b0) * H_;
#pragma unroll
        for (int mt = 0; mt < 2; ++mt)
#pragma unroll
            for (int rh = 0; rh < 2; ++rh) {
                const int row = mt * 16 + crow + rh * 8;
                float hn2[2];
#pragma unroll
                for (int col = 0; col < 2; ++col) {
                    const int q = rh * 2 + col;
                    const float bhr = (col == 0) ? bhv[0].x : bhv[0].y;
                    const float bhz = (col == 0) ? bhv[1].x : bhv[1].y;
                    const float bhn = (col == 0) ? bhv[2].x : bhv[2].y;
                    const float bir = (col == 0) ? biv[0].x : biv[0].y;
                    const float biz = (col == 0) ? biv[1].x : biv[1].y;
                    const float bin = (col == 0) ? biv[2].x : biv[2].y;
                    const float rg = sigf(bir + c[mt][0][q] + bhr);
                    const float zg = sigf(biz + c[mt][1][q] + bhz);
                    const float ng = tanh_f(bin + cx[mt][q] + rg * (c[mt][2][q] + bhn));
                    const float hv = ng + zg * (hold[mt][q] - ng);
                    hold[mt][q] = hv;
                    hn2[col] = hv;
                }
                *(float2*)&op[(size_t)row * H_ + jc] = make_float2(hn2[0], hn2[1]);
                *(uint32_t*)&hb[pn * 32 * HP2 + row * HP2 + jc] =
                    pack_h2(__float2half_rn(hn2[0]), __float2half_rn(hn2[1]));
            }

        if (FUSED) {
#pragma unroll
            for (int mt = 0; mt < 2; ++mt)
#pragma unroll
                for (int rh = 0; rh < 2; ++rh) {
                    const int row = mt * 16 + crow + rh * 8;
                    *(uint32_t*)&xb[pn * 32 * HP2 + row * HP2 + jc] =
                        pack_h2(__float2half_rn(xr[mt][rh].x), __float2half_rn(xr[mt][rh].y));
                }
        }
        __syncthreads();
    }
}

// ---------------------------------------------------------------------------
// fc1 (fp32, tiny)
// ---------------------------------------------------------------------------
__global__ void __launch_bounds__(256, 1)
fc1_kernel(const float* __restrict__ z, const float* __restrict__ c,
           const float* __restrict__ w, const float* __restrict__ bias,
           float* __restrict__ h0out)
{
    extern __shared__ float sm[];
    float* wc_s = sm;
    float* xc_s = wc_s + KC * NFCP;

    const int tid = threadIdx.x;
    const int cx  = tid & 31;
    const int ry  = tid >> 5;
    const int b0  = blockIdx.x * NB_;

    float acc[4][12];
#pragma unroll
    for (int m = 0; m < 4; ++m)
#pragma unroll
        for (int i = 0; i < 12; ++i) acc[m][i] = 0.f;

    for (int kc = 0; kc < KIN; kc += KC) {
        for (int idx = tid; idx < NFC * KC; idx += 256) {
            int g = idx / KC, kk = idx - g * KC;
            wc_s[kk * NFCP + g] = w[(size_t)g * KIN + kc + kk];
        }
        for (int idx = tid; idx < NB_ * KC; idx += 256) {
            int r = idx / KC, kk = idx - r * KC;
            int k = kc + kk;
            float v = (k < 256) ? z[(size_t)(b0 + r) * 256 + k]
                                : c[(size_t)(b0 + r) * 256 + (k - 256)];
            xc_s[kk * HPf + r] = v;
        }
        __syncthreads();
#pragma unroll 4
        for (int kk = 0; kk < KC; ++kk) {
            const float a0 = xc_s[kk * HPf + ry +  0];
            const float a1 = xc_s[kk * HPf + ry +  8];
            const float a2 = xc_s[kk * HPf + ry + 16];
            const float a3 = xc_s[kk * HPf + ry + 24];
            const float* wr = wc_s + kk * NFCP + cx;
#pragma unroll
            for (int i = 0; i < 12; ++i) {
                const float wv = wr[32 * i];
                acc[0][i] = fmaf(a0, wv, acc[0][i]);
                acc[1][i] = fmaf(a1, wv, acc[1][i]);
                acc[2][i] = fmaf(a2, wv, acc[2][i]);
                acc[3][i] = fmaf(a3, wv, acc[3][i]);
            }
        }
        __syncthreads();
    }

#pragma unroll
    for (int m = 0; m < 4; ++m) {
        const int r = b0 + ry + 8 * m;
#pragma unroll
        for (int i = 0; i < 12; ++i) {
            const int g = cx + 32 * i;
            float v = acc[m][i] + bias[g];
            v = (v >= 0.f) ? v : 0.2f * v;
            h0out[(size_t)r * NFC + g] = v;
        }
    }
}

// ---------------------------------------------------------------------------
// [T,B,H] -> [B,H,T] transpose
// ---------------------------------------------------------------------------
__global__ void transpose_kernel(const float* __restrict__ in, float* __restrict__ outp)
{
    __shared__ float tile[32][33];
    const int b  = blockIdx.z;
    const int j0 = blockIdx.y * 32;
    const int t0 = blockIdx.x * 32;
    const int tx = threadIdx.x, ty = threadIdx.y;

#pragma unroll
    for (int yy = ty; yy < 32; yy += 8) {
        const int t = t0 + yy;
        if (t < T_) tile[yy][tx] = in[((size_t)t * B_ + b) * H_ + j0 + tx];
    }
    __syncthreads();
#pragma unroll
    for (int yy = ty; yy < 32; yy += 8) {
        const int t = t0 + tx;
        const int j = j0 + yy;
        if (t < T_) outp[((size_t)b * H_ + j) * T_ + t] = tile[tx][yy];
    }
}

// ---------------------------------------------------------------------------
extern "C" void kernel_launch(void* const* d_in, const int* in_sizes, int n_in,
                              void* d_out, int out_size)
{
    const float* z     = (const float*)d_in[0];
    const float* c     = (const float*)d_in[1];
    const float* fc1_w = (const float*)d_in[2];
    const float* fc1_b = (const float*)d_in[3];
    const float* w_ih  = (const float*)d_in[4];
    const float* w_hh  = (const float*)d_in[5];
    const float* b_ih  = (const float*)d_in[6];
    const float* b_hh  = (const float*)d_in[7];
    float* out = (float*)d_out;

    float *bufA, *bufB, *h0Buf;
    cudaGetSymbolAddress((void**)&bufA,  g_bufA);
    cudaGetSymbolAddress((void**)&bufB,  g_bufB);
    cudaGetSymbolAddress((void**)&h0Buf, g_h0);

    const size_t smF = (size_t)(2 * G_ * PW + 4 * 32 * HP2) * sizeof(__half)
                     + (size_t)(2 * G_) * sizeof(float);        // ~148.7 KB
    const size_t sm0 = (size_t)(2 * 32 * HP2) * sizeof(__half)
                     + (size_t)(2 * G_) * sizeof(float);        // ~15.6 KB
    const size_t fcSm = (size_t)(KC * NFCP + KC * HPf) * sizeof(float);

    cudaFuncSetAttribute(scanF<false>, cudaFuncAttributeMaxDynamicSharedMemorySize, (int)sm0);
    cudaFuncSetAttribute(scanF<true>,  cudaFuncAttributeMaxDynamicSharedMemorySize, (int)smF);
    cudaFuncSetAttribute(fc1_kernel,   cudaFuncAttributeMaxDynamicSharedMemorySize, (int)fcSm);

    const int nblk = B_ / NB_;  // 128

    fc1_kernel<<<nblk, 256, fcSm>>>(z, c, fc1_w, fc1_b, h0Buf);

    // layer 0: input zeros
    scanF<false><<<nblk, 384, sm0>>>(w_hh, b_hh, nullptr, b_ih, h0Buf, nullptr, bufA);

    // layers 1..3: fused gi + scan
    const float* srcs[3] = {bufA, bufB, bufA};
    float*       dsts[3] = {bufB, bufA, bufB};
    for (int l = 1; l < 4; ++l) {
        const size_t wo = (size_t)l * G_ * H_;
        const size_t bo = (size_t)l * G_;
        scanF<true><<<nblk, 384, smF>>>(w_hh + wo, b_hh + bo, w_ih + wo, b_ih + bo,
                                        h0Buf + (size_t)l * B_ * H_, srcs[l - 1], dsts[l - 1]);
    }

    transpose_kernel<<<dim3(8, 3, B_), dim3(32, 8)>>>(bufB, out);
}

// round 9
// speedup vs baseline: 2.0502x; 1.0282x over previous
#include <cuda_runtime.h>
#include <cuda_fp16.h>
#include <cstdint>
#include <cstddef>

// ---------------------------------------------------------------------------
constexpr int H_  = 96;
constexpr int G_  = 288;
constexpr int T_  = 239;
constexpr int B_  = 4096;
constexpr int NB_ = 32;
constexpr int HW  = 48;    // H/2 packed words per row

constexpr int HP2 = 104;   // fp16 pitch for A (h/x) ldmatrix tiles
constexpr int PW  = 104;   // fp16 pitch for w_ih smem rows

constexpr int KIN  = 512;
constexpr int NFC  = 384;
constexpr int NFCP = 385;
constexpr int KC   = 64;
constexpr int HPf  = 33;

constexpr size_t SZ_X16 = (size_t)T_ * B_ * HW;   // packed fp16 activations
constexpr size_t SZ_H0  = (size_t)B_ * NFC;

__device__ uint32_t g_x16A[SZ_X16];
__device__ uint32_t g_x16B[SZ_X16];
__device__ float    g_h0  [SZ_H0];

// ---------------------------------------------------------------------------
__device__ __forceinline__ float sigf(float x)   { return 1.0f / (1.0f + __expf(-x)); }
__device__ __forceinline__ float tanh_f(float x) { return 2.0f / (1.0f + __expf(-2.0f * x)) - 1.0f; }

__device__ __forceinline__ uint32_t pack_h2(__half a, __half b) {
    return (uint32_t)__half_as_ushort(a) | ((uint32_t)__half_as_ushort(b) << 16);
}
__device__ __forceinline__ void split2h(float x, __half& h, __half& l) {
    h = __float2half_rn(x);
    l = __float2half_rn(x - __half2float(h));
}

__device__ __forceinline__ void mma16816(float c[4], const uint32_t a[4], const uint32_t b[2]) {
    asm volatile(
        "mma.sync.aligned.m16n8k16.row.col.f32.f16.f16.f32 "
        "{%0,%1,%2,%3}, {%4,%5,%6,%7}, {%8,%9}, {%0,%1,%2,%3};"
        : "+f"(c[0]), "+f"(c[1]), "+f"(c[2]), "+f"(c[3])
        : "r"(a[0]), "r"(a[1]), "r"(a[2]), "r"(a[3]), "r"(b[0]), "r"(b[1]));
}
__device__ __forceinline__ void ldsm4(uint32_t r[4], uint32_t addr) {
    asm volatile("ldmatrix.sync.aligned.m8n8.x4.shared.b16 {%0,%1,%2,%3}, [%4];"
                 : "=r"(r[0]), "=r"(r[1]), "=r"(r[2]), "=r"(r[3]) : "r"(addr));
}
__device__ __forceinline__ void cpasync16(uint32_t smem_addr, const void* gptr) {
    asm volatile("cp.async.cg.shared.global [%0], [%1], 16;" :: "r"(smem_addr), "l"(gptr));
}
__device__ __forceinline__ void cpasync_commit() {
    asm volatile("cp.async.commit_group;" ::: "memory");
}
__device__ __forceinline__ void cpasync_wait0() {
    asm volatile("cp.async.wait_group 0;" ::: "memory");
}

// ---------------------------------------------------------------------------
// Fused GRU scan, fp16: A single fp16 (streamed via cp.async), weights 2-term.
// 384 threads = 12 warps; warp w owns j in [8w,8w+8), gate cols +0,+96,+192.
// Intermediate activations live as packed fp16 in gmem. LAST layer writes
// the [B,H,T] output directly (transpose folded in).
// ---------------------------------------------------------------------------
template <bool FUSED, bool LAST>
__global__ void __launch_bounds__(384, 1)
scanF(const float* __restrict__ w_hh, const float* __restrict__ b_hh,
      const float* __restrict__ w_ih, const float* __restrict__ b_ih,
      const float* __restrict__ h0,   const uint32_t* __restrict__ xg,
      uint32_t* __restrict__ outg,    float* __restrict__ outf)
{
    extern __shared__ __align__(16) char smraw[];
    __half* wHi = (__half*)smraw;
    __half* wLo = wHi + (FUSED ? G_ * PW : 0);
    __half* hb  = wLo + (FUSED ? G_ * PW : 0);      // [2 phases][32*HP2]
    __half* xb  = hb + 2 * 32 * HP2;                // [2 phases][32*HP2] (FUSED)
    float* bias_s = (float*)(xb + (FUSED ? 2 * 32 * HP2 : 0));

    const int tid  = threadIdx.x;
    const int lane = tid & 31;
    const int w    = tid >> 5;          // 0..11
    const int b0   = blockIdx.x * NB_;

    // --- w_hh 2-term fp16 fragments in registers ---
    uint32_t bhi[6][3][2], blo[6][3][2];
#pragma unroll
    for (int kt = 0; kt < 6; ++kt)
#pragma unroll
        for (int nt = 0; nt < 3; ++nt) {
            const int g  = nt * 96 + 8 * w + (lane >> 2);
            const int k0 = kt * 16 + (lane & 3) * 2;
            const float* p = w_hh + (size_t)g * H_ + k0;
            float w0 = p[0], w1 = p[1], w2 = p[8], w3 = p[9];
            __half h0b, h1b, h2b, h3b, l0b, l1b, l2b, l3b;
            split2h(w0, h0b, l0b); split2h(w1, h1b, l1b);
            split2h(w2, h2b, l2b); split2h(w3, h3b, l3b);
            bhi[kt][nt][0] = pack_h2(h0b, h1b);
            bhi[kt][nt][1] = pack_h2(h2b, h3b);
            blo[kt][nt][0] = pack_h2(l0b, l1b);
            blo[kt][nt][1] = pack_h2(l2b, l3b);
        }

    // --- w_ih 2-term split into smem (FUSED only) ---
    if constexpr (FUSED) {
        for (int i = tid; i < G_ * H_; i += 384) {
            const int g = i / H_, k = i - g * H_;
            __half h, l; split2h(w_ih[i], h, l);
            wHi[g * PW + k] = h;
            wLo[g * PW + k] = l;
        }
    }
    if (tid < G_) {
        bias_s[tid]      = b_hh[tid];
        bias_s[G_ + tid] = b_ih[tid];
    }

    const int crow = lane >> 2;
    const int jc   = 8 * w + 2 * (lane & 3);

    // --- init h state: registers + single fp16 buffer (phase 0) ---
    float hold[2][4];
#pragma unroll
    for (int mt = 0; mt < 2; ++mt)
#pragma unroll
        for (int rh = 0; rh < 2; ++rh) {
            const int row = mt * 16 + crow + rh * 8;
            const float2 v = *(const float2*)&h0[(size_t)(b0 + row) * H_ + jc];
            hold[mt][rh * 2]     = v.x;
            hold[mt][rh * 2 + 1] = v.y;
            *(uint32_t*)&hb[0 * 32 * HP2 + row * HP2 + jc] =
                pack_h2(__float2half_rn(v.x), __float2half_rn(v.y));
        }

    // --- cp.async mapping: 384 threads = 32 rows x 12 chunks of 16B ---
    const int cprow   = tid / 12;
    const int cpchunk = tid - cprow * 12;
    const uint32_t xbS = (uint32_t)__cvta_generic_to_shared(xb)
                       + (uint32_t)(cprow * HP2 * 2 + cpchunk * 16);
    const uint32_t* xsrc0 = nullptr;
    if constexpr (FUSED) {
        xsrc0 = xg + (size_t)(b0 + cprow) * HW + cpchunk * 4;
        // prologue: x(0) -> xb phase 0
        cpasync16(xbS, xsrc0);
        cpasync_commit();
        cpasync_wait0();
    }
    __syncthreads();

    // ldmatrix per-lane offsets
    const int arow = (lane & 7) + ((lane >> 3) & 1) * 8;
    const int acol = ((lane >> 4) & 1) * 8;
    const uint32_t lofs = (uint32_t)((arow * HP2 + acol) * 2);
    const uint32_t hBase = (uint32_t)__cvta_generic_to_shared(hb) + lofs;
    const uint32_t xBase = (uint32_t)__cvta_generic_to_shared(xb) + lofs;
    constexpr uint32_t BUFB = (uint32_t)(32 * HP2 * 2);

    const int wcol0 = 8 * w + (lane >> 2);
    const int wk0   = (lane & 3) * 2;

    for (int t = 0; t < T_; ++t) {
        const int p  = t & 1;
        const int pn = p ^ 1;

        // stream x(t+1) into xb[pn] (async; waited before end-of-step barrier)
        if constexpr (FUSED) {
            const int tn = (t + 1 < T_) ? (t + 1) : (T_ - 1);
            cpasync16(xbS + (uint32_t)pn * BUFB, xsrc0 + (size_t)tn * B_ * HW);
            cpasync_commit();
        }

        float c[2][3][4];   // r, z, n(hidden)
        float cx[2][4];     // n(input) — separate (stays outside r*(...))
#pragma unroll
        for (int mt = 0; mt < 2; ++mt) {
#pragma unroll
            for (int nt = 0; nt < 3; ++nt)
#pragma unroll
                for (int q = 0; q < 4; ++q) c[mt][nt][q] = 0.f;
#pragma unroll
            for (int q = 0; q < 4; ++q) cx[mt][q] = 0.f;
        }

        const uint32_t aH = hBase + (uint32_t)p * BUFB;
        const uint32_t aX = xBase + (uint32_t)p * BUFB;

#pragma unroll
        for (int kt = 0; kt < 6; ++kt) {
            const uint32_t o = (uint32_t)(kt * 32);
            uint32_t ah0[4], ah1[4];
            ldsm4(ah0, aH + o);
            ldsm4(ah1, aH + o + 16 * HP2 * 2);
#pragma unroll
            for (int nt = 0; nt < 3; ++nt) {
                mma16816(c[0][nt], ah0, bhi[kt][nt]);
                mma16816(c[1][nt], ah1, bhi[kt][nt]);
            }
#pragma unroll
            for (int nt = 0; nt < 3; ++nt) {
                mma16816(c[0][nt], ah0, blo[kt][nt]);
                mma16816(c[1][nt], ah1, blo[kt][nt]);
            }
            if constexpr (FUSED) {
                uint32_t xh0[4], xh1[4];
                ldsm4(xh0, aX + o);
                ldsm4(xh1, aX + o + 16 * HP2 * 2);
                uint32_t bxh[3][2], bxl[3][2];
#pragma unroll
                for (int nt = 0; nt < 3; ++nt) {
                    const int cidx = (nt * 96 + wcol0) * PW + kt * 16 + wk0;
                    bxh[nt][0] = *(const uint32_t*)&wHi[cidx];
                    bxh[nt][1] = *(const uint32_t*)&wHi[cidx + 8];
                    bxl[nt][0] = *(const uint32_t*)&wLo[cidx];
                    bxl[nt][1] = *(const uint32_t*)&wLo[cidx + 8];
                }
                // x GEMM: r,z -> c[][0..1]; n -> cx (separate!)
                mma16816(c[0][0], xh0, bxh[0]);
                mma16816(c[1][0], xh1, bxh[0]);
                mma16816(c[0][1], xh0, bxh[1]);
                mma16816(c[1][1], xh1, bxh[1]);
                mma16816(cx[0],   xh0, bxh[2]);
                mma16816(cx[1],   xh1, bxh[2]);

                mma16816(c[0][0], xh0, bxl[0]);
                mma16816(c[1][0], xh1, bxl[0]);
                mma16816(c[0][1], xh0, bxl[1]);
                mma16816(c[1][1], xh1, bxl[1]);
                mma16816(cx[0],   xh0, bxl[2]);
                mma16816(cx[1],   xh1, bxl[2]);
            }
        }

        float2 bhv[3], biv[3];
#pragma unroll
        for (int g = 0; g < 3; ++g) {
            bhv[g] = *(const float2*)&bias_s[g * 96 + jc];
            biv[g] = *(const float2*)&bias_s[G_ + g * 96 + jc];
        }

#pragma unroll
        for (int mt = 0; mt < 2; ++mt)
#pragma unroll
            for (int rh = 0; rh < 2; ++rh) {
                const int row = mt * 16 + crow + rh * 8;
                float hn2[2];
#pragma unroll
                for (int col = 0; col < 2; ++col) {
                    const int q = rh * 2 + col;
                    const float bhr = (col == 0) ? bhv[0].x : bhv[0].y;
                    const float bhz = (col == 0) ? bhv[1].x : bhv[1].y;
                    const float bhn = (col == 0) ? bhv[2].x : bhv[2].y;
                    const float bir = (col == 0) ? biv[0].x : biv[0].y;
                    const float biz = (col == 0) ? biv[1].x : biv[1].y;
                    const float bin = (col == 0) ? biv[2].x : biv[2].y;
                    const float rg = sigf(bir + c[mt][0][q] + bhr);
                    const float zg = sigf(biz + c[mt][1][q] + bhz);
                    const float ng = tanh_f(bin + cx[mt][q] + rg * (c[mt][2][q] + bhn));
                    const float hv = ng + zg * (hold[mt][q] - ng);
                    hold[mt][q] = hv;
                    hn2[col] = hv;
                }
                const uint32_t ph = pack_h2(__float2half_rn(hn2[0]), __float2half_rn(hn2[1]));
                *(uint32_t*)&hb[pn * 32 * HP2 + row * HP2 + jc] = ph;
                if constexpr (LAST) {
                    const int ob = ((b0 + row) * H_ + jc) * T_ + t;
                    outf[ob]      = hn2[0];
                    outf[ob + T_] = hn2[1];
                } else {
                    outg[(size_t)(t * B_ + b0 + row) * HW + (jc >> 1)] = ph;
                }
            }

        if constexpr (FUSED) cpasync_wait0();
        __syncthreads();
    }
}

// ---------------------------------------------------------------------------
// fc1 (fp32, tiny)
// ---------------------------------------------------------------------------
__global__ void __launch_bounds__(256, 1)
fc1_kernel(const float* __restrict__ z, const float* __restrict__ c,
           const float* __restrict__ w, const float* __restrict__ bias,
           float* __restrict__ h0out)
{
    extern __shared__ float sm[];
    float* wc_s = sm;
    float* xc_s = wc_s + KC * NFCP;

    const int tid = threadIdx.x;
    const int cx  = tid & 31;
    const int ry  = tid >> 5;
    const int b0  = blockIdx.x * NB_;

    float acc[4][12];
#pragma unroll
    for (int m = 0; m < 4; ++m)
#pragma unroll
        for (int i = 0; i < 12; ++i) acc[m][i] = 0.f;

    for (int kc = 0; kc < KIN; kc += KC) {
        for (int idx = tid; idx < NFC * KC; idx += 256) {
            int g = idx / KC, kk = idx - g * KC;
            wc_s[kk * NFCP + g] = w[(size_t)g * KIN + kc + kk];
        }
        for (int idx = tid; idx < NB_ * KC; idx += 256) {
            int r = idx / KC, kk = idx - r * KC;
            int k = kc + kk;
            float v = (k < 256) ? z[(size_t)(b0 + r) * 256 + k]
                                : c[(size_t)(b0 + r) * 256 + (k - 256)];
            xc_s[kk * HPf + r] = v;
        }
        __syncthreads();
#pragma unroll 4
        for (int kk = 0; kk < KC; ++kk) {
            const float a0 = xc_s[kk * HPf + ry +  0];
            const float a1 = xc_s[kk * HPf + ry +  8];
            const float a2 = xc_s[kk * HPf + ry + 16];
            const float a3 = xc_s[kk * HPf + ry + 24];
            const float* wr = wc_s + kk * NFCP + cx;
#pragma unroll
            for (int i = 0; i < 12; ++i) {
                const float wv = wr[32 * i];
                acc[0][i] = fmaf(a0, wv, acc[0][i]);
                acc[1][i] = fmaf(a1, wv, acc[1][i]);
                acc[2][i] = fmaf(a2, wv, acc[2][i]);
                acc[3][i] = fmaf(a3, wv, acc[3][i]);
            }
        }
        __syncthreads();
    }

#pragma unroll
    for (int m = 0; m < 4; ++m) {
        const int r = b0 + ry + 8 * m;
#pragma unroll
        for (int i = 0; i < 12; ++i) {
            const int g = cx + 32 * i;
            float v = acc[m][i] + bias[g];
            v = (v >= 0.f) ? v : 0.2f * v;
            h0out[(size_t)r * NFC + g] = v;
        }
    }
}

// ---------------------------------------------------------------------------
extern "C" void kernel_launch(void* const* d_in, const int* in_sizes, int n_in,
                              void* d_out, int out_size)
{
    const float* z     = (const float*)d_in[0];
    const float* c     = (const float*)d_in[1];
    const float* fc1_w = (const float*)d_in[2];
    const float* fc1_b = (const float*)d_in[3];
    const float* w_ih  = (const float*)d_in[4];
    const float* w_hh  = (const float*)d_in[5];
    const float* b_ih  = (const float*)d_in[6];
    const float* b_hh  = (const float*)d_in[7];
    float* out = (float*)d_out;

    uint32_t *xA, *xB;
    float *h0Buf;
    cudaGetSymbolAddress((void**)&xA,    g_x16A);
    cudaGetSymbolAddress((void**)&xB,    g_x16B);
    cudaGetSymbolAddress((void**)&h0Buf, g_h0);

    const size_t smF = (size_t)(2 * G_ * PW + 4 * 32 * HP2) * sizeof(__half)
                     + (size_t)(2 * G_) * sizeof(float);        // ~148.7 KB
    const size_t sm0 = (size_t)(2 * 32 * HP2) * sizeof(__half)
                     + (size_t)(2 * G_) * sizeof(float);        // ~15.6 KB
    const size_t fcSm = (size_t)(KC * NFCP + KC * HPf) * sizeof(float);

    cudaFuncSetAttribute((const void*)scanF<false, false>, cudaFuncAttributeMaxDynamicSharedMemorySize, (int)sm0);
    cudaFuncSetAttribute((const void*)scanF<true,  false>, cudaFuncAttributeMaxDynamicSharedMemorySize, (int)smF);
    cudaFuncSetAttribute((const void*)scanF<true,  true>,  cudaFuncAttributeMaxDynamicSharedMemorySize, (int)smF);
    cudaFuncSetAttribute((const void*)fc1_kernel,           cudaFuncAttributeMaxDynamicSharedMemorySize, (int)fcSm);

    const int nblk = B_ / NB_;  // 128

    fc1_kernel<<<nblk, 256, fcSm>>>(z, c, fc1_w, fc1_b, h0Buf);

    // layer 0: input zeros -> fp16 activations into xA
    scanF<false, false><<<nblk, 384, sm0>>>(w_hh, b_hh, nullptr, b_ih,
                                            h0Buf, nullptr, xA, nullptr);

    // layer 1: xA -> xB
    scanF<true, false><<<nblk, 384, smF>>>(w_hh + 1 * (size_t)G_ * H_, b_hh + 1 * G_,
                                           w_ih + 1 * (size_t)G_ * H_, b_ih + 1 * G_,
                                           h0Buf + 1 * (size_t)B_ * H_, xA, xB, nullptr);
    // layer 2: xB -> xA
    scanF<true, false><<<nblk, 384, smF>>>(w_hh + 2 * (size_t)G_ * H_, b_hh + 2 * G_,
                                           w_ih + 2 * (size_t)G_ * H_, b_ih + 2 * G_,
                                           h0Buf + 2 * (size_t)B_ * H_, xB, xA, nullptr);
    // layer 3: xA -> out [B,H,T] directly (transpose folded in)
    scanF<true, true><<<nblk, 384, smF>>>(w_hh + 3 * (size_t)G_ * H_, b_hh + 3 * G_,
                                          w_ih + 3 * (size_t)G_ * H_, b_ih + 3 * G_,
                                          h0Buf + 3 * (size_t)B_ * H_, xA, nullptr, out);
}